// round 2
// baseline (speedup 1.0000x reference)
#include <cuda_runtime.h>
#include <cuda_bf16.h>

#define A_N      4096
#define N_OBJ    8192
#define IN_DIM   16
#define EMBED    128
#define MAX_OBJ  16
#define DEG      8
#define OBS_DEG  8
#define POS_DIM  2
#define ORIG     18          // IN_DIM + POS_DIM
#define ORIG_P   20          // padded row stride (80B, 16B aligned)
#define OUTC     288         // MAX_OBJ * ORIG
#define NLOG     17          // MAX_OBJ + 1
#define KTOT     128         // DEG * MAX_OBJ
#define THRES    0.02f

typedef unsigned long long ull;

__device__ __forceinline__ ull f2fma(ull a, ull b, ull c) {
    ull d;
    asm("fma.rn.f32x2 %0, %1, %2, %3;" : "=l"(d) : "l"(a), "l"(b), "l"(c));
    return d;
}
__device__ __forceinline__ float f2sum(ull v) {
    float lo, hi;
    asm("mov.b64 {%0, %1}, %2;" : "=f"(lo), "=f"(hi) : "l"(v));
    return lo + hi;
}
__device__ __forceinline__ ull f2pack(float lo, float hi) {
    ull v;
    asm("mov.b64 %0, {%1, %2};" : "=l"(v) : "f"(lo), "f"(hi));
    return v;
}

// ---------------- device scratch ----------------
__device__ float  g_enc[A_N * EMBED];
// k-quad interleaved weight layouts: Q[kq*cols + c] = {W[4kq][c], W[4kq+1][c], W[4kq+2][c], W[4kq+3][c]}
__device__ float4 g_mdec_WxQ[32 * OUTC];
__device__ float4 g_dec_WxQ [32 * OUTC];
__device__ float4 g_enc_W2Q [32 * EMBED];
__device__ float4 g_menc_W2Q[32 * EMBED];
__device__ float4 g_mdec_WsQ[32 * NLOG];
__device__ float4 g_dec_WsQ [32 * NLOG];

#define PREP_TOTAL (2 * 32 * OUTC + 2 * 32 * EMBED + 2 * 32 * NLOG)

__device__ __forceinline__ float4 quad(const float* __restrict__ W, int cols, int kq, int c) {
    return make_float4(W[(4 * kq    ) * cols + c], W[(4 * kq + 1) * cols + c],
                       W[(4 * kq + 2) * cols + c], W[(4 * kq + 3) * cols + c]);
}

__global__ void prep_kernel(const float* __restrict__ mWx, const float* __restrict__ dWx,
                            const float* __restrict__ eW2, const float* __restrict__ mW2,
                            const float* __restrict__ mWs, const float* __restrict__ dWs) {
    int idx = blockIdx.x * blockDim.x + threadIdx.x;
    if (idx < 32 * OUTC) { g_mdec_WxQ[idx] = quad(mWx, OUTC, idx / OUTC, idx % OUTC); return; }
    idx -= 32 * OUTC;
    if (idx < 32 * OUTC) { g_dec_WxQ[idx]  = quad(dWx, OUTC, idx / OUTC, idx % OUTC); return; }
    idx -= 32 * OUTC;
    if (idx < 32 * EMBED) { g_enc_W2Q[idx]  = quad(eW2, EMBED, idx / EMBED, idx % EMBED); return; }
    idx -= 32 * EMBED;
    if (idx < 32 * EMBED) { g_menc_W2Q[idx] = quad(mW2, EMBED, idx / EMBED, idx % EMBED); return; }
    idx -= 32 * EMBED;
    if (idx < 32 * NLOG) { g_mdec_WsQ[idx] = quad(mWs, NLOG, idx / NLOG, idx % NLOG); return; }
    idx -= 32 * NLOG;
    if (idx < 32 * NLOG) { g_dec_WsQ[idx]  = quad(dWs, NLOG, idx / NLOG, idx % NLOG); return; }
}

// ---------------------------------------------------------------------------
// Kernel A: obs encode.  One block per agent, 128 threads.
// ---------------------------------------------------------------------------
__global__ __launch_bounds__(128) void enc_kernel(
    const float* __restrict__ obj_x, const float* __restrict__ obj_pos,
    const float* __restrict__ agent_pos,
    const float* __restrict__ W1, const float* __restrict__ b1,
    const float* __restrict__ b2,
    const int*   __restrict__ obs_src)
{
    const int a = blockIdx.x;
    const int t = threadIdx.x;

    __shared__ __align__(16) float msg[OBS_DEG][ORIG_P];
    __shared__ __align__(16) float S[EMBED];
    __shared__ float apos[2];

    if (t < 2) apos[t] = agent_pos[2 * a + t];
    __syncthreads();

    for (int idx = t; idx < OBS_DEG * ORIG; idx += 128) {
        const int e = idx / ORIG;
        const int k = idx - e * ORIG;
        const int o = obs_src[a * OBS_DEG + e];
        float v;
        if (k < IN_DIM) v = obj_x[o * IN_DIM + k];
        else            v = obj_pos[o * POS_DIM + (k - IN_DIM)] - apos[k - IN_DIM];
        msg[e][k] = v;
    }
    __syncthreads();

    // pack W1 column t into 9 f32x2 pairs
    ull w1p[9];
#pragma unroll
    for (int q = 0; q < 9; q++)
        w1p[q] = f2pack(W1[(2 * q) * EMBED + t], W1[(2 * q + 1) * EMBED + t]);
    const float b1t = b1[t];

    float acc = 0.f;
#pragma unroll
    for (int e = 0; e < OBS_DEG; e++) {
        const ulonglong2* r = (const ulonglong2*)msg[e];
        ulonglong2 q0 = r[0], q1 = r[1], q2 = r[2], q3 = r[3];
        ull q4 = ((const ull*)msg[e])[8];
        ull h = 0;
        h = f2fma(q0.x, w1p[0], h); h = f2fma(q0.y, w1p[1], h);
        h = f2fma(q1.x, w1p[2], h); h = f2fma(q1.y, w1p[3], h);
        h = f2fma(q2.x, w1p[4], h); h = f2fma(q2.y, w1p[5], h);
        h = f2fma(q3.x, w1p[6], h); h = f2fma(q3.y, w1p[7], h);
        h = f2fma(q4,   w1p[8], h);
        acc += fmaxf(f2sum(h) + b1t, 0.f);
    }
    S[t] = acc;
    __syncthreads();

    ull ao = 0;
    const ulonglong2* WQ = (const ulonglong2*)g_enc_W2Q;
#pragma unroll 4
    for (int kq = 0; kq < 32; kq++) {
        ulonglong2 w = WQ[kq * EMBED + t];
        ulonglong2 z = *(const ulonglong2*)&S[4 * kq];
        ao = f2fma(z.x, w.x, ao);
        ao = f2fma(z.y, w.y, ao);
    }
    g_enc[a * EMBED + t] = f2sum(ao) + b2[t];
}

// ---------------------------------------------------------------------------
// Kernel B: per-agent comm decode + dedup + merge + final decode.
// ---------------------------------------------------------------------------
__global__ __launch_bounds__(128) void agent_kernel(
    const float* __restrict__ agent_pos,
    const float* __restrict__ mdec_bs, const float* __restrict__ mdec_bx,
    const float* __restrict__ menc_W1, const float* __restrict__ menc_b1,
    const float* __restrict__ menc_b2,
    const float* __restrict__ dec_bs,  const float* __restrict__ dec_bx,
    const int*   __restrict__ comm_src,
    float* __restrict__ out, int write_extra)
{
    const int i = blockIdx.x;
    const int t = threadIdx.x;
    const int lane = t & 31;
    const int wrp  = t >> 5;

    __shared__ __align__(16) float zj[DEG][EMBED];       // 4 KB
    __shared__ __align__(16) float cand[KTOT][ORIG_P];   // 10 KB (aliased as dout later)
    __shared__ __align__(16) float Spre[EMBED];
    __shared__ __align__(16) float mergeds[EMBED];
    __shared__ float logits[DEG][NLOG];
    __shared__ int   npred[DEG];
    __shared__ int   keepf[KTOT];
    __shared__ float cpx[KTOT], cpy[KTOT];
    __shared__ int   cidx[KTOT];
    __shared__ float relx[DEG], rely[DEG];
    __shared__ int   jidx[DEG];
    __shared__ float dlog[NLOG];
    __shared__ int   kidx[MAX_OBJ];
    __shared__ int   wtot[4], wtot2[4];
    __shared__ int   n2s;

    if (t < DEG) {
        const int j = comm_src[i * DEG + t];
        jidx[t] = j;
        relx[t] = agent_pos[2 * j    ] - agent_pos[2 * i    ];
        rely[t] = agent_pos[2 * j + 1] - agent_pos[2 * i + 1];
    }
    __syncthreads();
#pragma unroll
    for (int e = 0; e < DEG; e++) zj[e][t] = g_enc[jidx[e] * EMBED + t];
    __syncthreads();

    // ---- mdec elems: 288 cols in 3 rounds (round 2: threads<32) ----
    {
        const ulonglong2* WQ = (const ulonglong2*)g_mdec_WxQ;
#pragma unroll 1
        for (int ci = 0; ci < 3; ci++) {
            const int c = t + ci * 128;
            if (ci < 2 || t < 32) {
                ull acc[DEG];
#pragma unroll
                for (int e = 0; e < DEG; e++) acc[e] = 0;
#pragma unroll 2
                for (int kq = 0; kq < 32; kq++) {
                    ulonglong2 w = WQ[kq * OUTC + c];
#pragma unroll
                    for (int e = 0; e < DEG; e++) {
                        ulonglong2 z = *(const ulonglong2*)&zj[e][4 * kq];
                        acc[e] = f2fma(z.x, w.x, acc[e]);
                        acc[e] = f2fma(z.y, w.y, acc[e]);
                    }
                }
                const int m = c / ORIG;
                const int dim = c - m * ORIG;
                const float bx = mdec_bx[c];
#pragma unroll
                for (int e = 0; e < DEG; e++) {
                    float v = f2sum(acc[e]) + bx;
                    if (dim == 16) v += relx[e];
                    if (dim == 17) v += rely[e];
                    cand[e * MAX_OBJ + m][dim] = v;
                }
            }
        }
        // logits on threads 64..80 (runs concurrently with round 2 on warp 0)
        if (t >= 64 && t < 64 + NLOG) {
            const int s = t - 64;
            const ulonglong2* WsQ = (const ulonglong2*)g_mdec_WsQ;
            ull acc[DEG];
#pragma unroll
            for (int e = 0; e < DEG; e++) acc[e] = 0;
            for (int kq = 0; kq < 32; kq++) {
                ulonglong2 w = WsQ[kq * NLOG + s];
#pragma unroll
                for (int e = 0; e < DEG; e++) {
                    ulonglong2 z = *(const ulonglong2*)&zj[e][4 * kq];
                    acc[e] = f2fma(z.x, w.x, acc[e]);
                    acc[e] = f2fma(z.y, w.y, acc[e]);
                }
            }
            const float bs = mdec_bs[s];
#pragma unroll
            for (int e = 0; e < DEG; e++) logits[e][s] = f2sum(acc[e]) + bs;
        }
    }
    __syncthreads();

    // argmax per edge (first max)
    if (t < DEG) {
        float best = logits[t][0]; int bi = 0;
#pragma unroll
        for (int c = 1; c < NLOG; c++) {
            const float v = logits[t][c];
            if (v > best) { best = v; bi = c; }
        }
        npred[t] = bi;
    }
    __syncthreads();

    // ---- validity + compact + dedup ----
    const int em = t >> 4, mm = t & 15;
    const int v0 = (mm < npred[em]) ? 1 : 0;
    const float x0 = cand[t][16], y0 = cand[t][17];

    unsigned bm = __ballot_sync(0xffffffffu, v0);
    int pre = __popc(bm & ((1u << lane) - 1u));
    if (lane == 31) wtot[wrp] = pre + v0;
    keepf[t] = 0;
    __syncthreads();
    int off = 0;
#pragma unroll
    for (int q = 0; q < 4; q++) if (q < wrp) off += wtot[q];
    const int nv = wtot[0] + wtot[1] + wtot[2] + wtot[3];
    if (v0) { const int p = off + pre; cpx[p] = x0; cpy[p] = y0; cidx[p] = t; }
    __syncthreads();

    if (t < nv) {
        const float xx = cpx[t], yy = cpy[t];
        int dead = 0;
        for (int k = 0; k < t; k++) {
            const float dx = xx - cpx[k];
            const float dy = yy - cpy[k];
            if (sqrtf(fmaf(dx, dx, dy * dy)) < THRES) dead = 1;
        }
        if (!dead) keepf[cidx[t]] = 1;
    }
    __syncthreads();

    // ---- cap to 15 via prefix scan, compact kept indices ----
    const int k2 = keepf[t];
    unsigned bm2 = __ballot_sync(0xffffffffu, k2);
    int pre2 = __popc(bm2 & ((1u << lane) - 1u));
    if (lane == 31) wtot2[wrp] = pre2 + k2;
    __syncthreads();
    int off2 = 0;
#pragma unroll
    for (int q = 0; q < 4; q++) if (q < wrp) off2 += wtot2[q];
    const int tot2 = wtot2[0] + wtot2[1] + wtot2[2] + wtot2[3];
    const int ncnt = (tot2 < MAX_OBJ - 1) ? tot2 : (MAX_OBJ - 1);
    const int excl = off2 + pre2;
    if (k2 && (excl + 1 <= MAX_OBJ - 1)) kidx[excl] = t;
    __syncthreads();

    // ---- merge encode: Spre[t] = sum over kept of relu(cand . W1[:,t] + b1[t]) ----
    {
        ull w1p[9];
#pragma unroll
        for (int q = 0; q < 9; q++)
            w1p[q] = f2pack(menc_W1[(2 * q) * EMBED + t], menc_W1[(2 * q + 1) * EMBED + t]);
        const float b1t = menc_b1[t];
        float acc = 0.f;
        for (int l = 0; l < ncnt; l++) {
            const int li = kidx[l];
            const ulonglong2* r = (const ulonglong2*)cand[li];
            ulonglong2 q0 = r[0], q1 = r[1], q2 = r[2], q3 = r[3];
            ull q4 = ((const ull*)cand[li])[8];
            ull h = 0;
            h = f2fma(q0.x, w1p[0], h); h = f2fma(q0.y, w1p[1], h);
            h = f2fma(q1.x, w1p[2], h); h = f2fma(q1.y, w1p[3], h);
            h = f2fma(q2.x, w1p[4], h); h = f2fma(q2.y, w1p[5], h);
            h = f2fma(q3.x, w1p[6], h); h = f2fma(q3.y, w1p[7], h);
            h = f2fma(q4,   w1p[8], h);
            acc += fmaxf(f2sum(h) + b1t, 0.f);
        }
        Spre[t] = acc;
    }
    __syncthreads();

    // merged = Spre @ menc_W2 + b2
    {
        ull a = 0;
        const ulonglong2* WQ = (const ulonglong2*)g_menc_W2Q;
#pragma unroll 4
        for (int kq = 0; kq < 32; kq++) {
            ulonglong2 w = WQ[kq * EMBED + t];
            ulonglong2 z = *(const ulonglong2*)&Spre[4 * kq];
            a = f2fma(z.x, w.x, a);
            a = f2fma(z.y, w.y, a);
        }
        mergeds[t] = f2sum(a) + menc_b2[t];
    }
    __syncthreads();

    // ---- final decode (3 rounds) + dec logits on spare threads ----
    float* dout = &cand[0][0];   // cand dead now; reuse as dout[288]
    {
        const ulonglong2* WQ = (const ulonglong2*)g_dec_WxQ;
#pragma unroll 1
        for (int ci = 0; ci < 3; ci++) {
            const int c = t + ci * 128;
            if (ci < 2 || t < 32) {
                ull a = 0;
#pragma unroll 4
                for (int kq = 0; kq < 32; kq++) {
                    ulonglong2 w = WQ[kq * OUTC + c];
                    ulonglong2 z = *(const ulonglong2*)&mergeds[4 * kq];
                    a = f2fma(z.x, w.x, a);
                    a = f2fma(z.y, w.y, a);
                }
                dout[c] = f2sum(a) + dec_bx[c];
            }
        }
        if (t >= 64 && t < 64 + NLOG) {
            const int s = t - 64;
            const ulonglong2* WsQ = (const ulonglong2*)g_dec_WsQ;
            ull a = 0;
            for (int kq = 0; kq < 32; kq++) {
                ulonglong2 w = WsQ[kq * NLOG + s];
                ulonglong2 z = *(const ulonglong2*)&mergeds[4 * kq];
                a = f2fma(z.x, w.x, a);
                a = f2fma(z.y, w.y, a);
            }
            dlog[s] = f2sum(a) + dec_bs[s];
        }
    }
    __syncthreads();
    if (t == 0) {
        float best = dlog[0]; int bi = 0;
#pragma unroll
        for (int c = 1; c < NLOG; c++) {
            if (dlog[c] > best) { best = dlog[c]; bi = c; }
        }
        n2s = bi;
    }
    __syncthreads();
    const int n2 = n2s;

    // masked writes
    {
        int c = t;
        out[(size_t)i * OUTC + c] = ((c / ORIG) < n2) ? dout[c] : 0.f;
        c = t + 128;
        out[(size_t)i * OUTC + c] = ((c / ORIG) < n2) ? dout[c] : 0.f;
        if (t < 32) {
            c = t + 256;
            out[(size_t)i * OUTC + c] = ((c / ORIG) < n2) ? dout[c] : 0.f;
        }
    }
    if (write_extra && t < MAX_OBJ) {
        const size_t batch_off = (size_t)A_N * OUTC;
        const size_t mask_off  = batch_off + (size_t)A_N * MAX_OBJ;
        out[batch_off + (size_t)i * MAX_OBJ + t] = (float)i;
        out[mask_off  + (size_t)i * MAX_OBJ + t] = (t < n2) ? 1.f : 0.f;
    }
}

extern "C" void kernel_launch(void* const* d_in, const int* in_sizes, int n_in,
                              void* d_out, int out_size) {
    const float* obj_x     = (const float*)d_in[0];
    const float* obj_pos   = (const float*)d_in[1];
    const float* agent_pos = (const float*)d_in[2];
    const float* enc_W1    = (const float*)d_in[3];
    const float* enc_b1    = (const float*)d_in[4];
    const float* enc_W2    = (const float*)d_in[5];
    const float* enc_b2    = (const float*)d_in[6];
    const float* mdec_Ws   = (const float*)d_in[7];
    const float* mdec_bs   = (const float*)d_in[8];
    const float* mdec_Wx   = (const float*)d_in[9];
    const float* mdec_bx   = (const float*)d_in[10];
    const float* menc_W1   = (const float*)d_in[11];
    const float* menc_b1   = (const float*)d_in[12];
    const float* menc_W2   = (const float*)d_in[13];
    const float* menc_b2   = (const float*)d_in[14];
    const float* dec_Ws    = (const float*)d_in[15];
    const float* dec_bs    = (const float*)d_in[16];
    const float* dec_Wx    = (const float*)d_in[17];
    const float* dec_bx    = (const float*)d_in[18];
    const int*   obs_ei    = (const int*)d_in[19];   // row0 = tgt, row1 = src
    const int*   comm_ei   = (const int*)d_in[20];   // row0 = src(j), row1 = tgt(i)

    const int* obs_src  = obs_ei  + A_N * OBS_DEG;   // row 1
    const int* comm_src = comm_ei;                   // row 0

    prep_kernel<<<(PREP_TOTAL + 255) / 256, 256>>>(mdec_Wx, dec_Wx, enc_W2, menc_W2,
                                                   mdec_Ws, dec_Ws);

    enc_kernel<<<A_N, 128>>>(obj_x, obj_pos, agent_pos,
                             enc_W1, enc_b1, enc_b2, obs_src);

    const int full = A_N * OUTC + 2 * A_N * MAX_OBJ;   // decoded + batch + mask
    const int write_extra = (out_size >= full) ? 1 : 0;

    agent_kernel<<<A_N, 128>>>(agent_pos,
                               mdec_bs, mdec_bx,
                               menc_W1, menc_b1, menc_b2,
                               dec_bs, dec_bx,
                               comm_src, (float*)d_out, write_extra);
}

// round 3
// speedup vs baseline: 1.0558x; 1.0558x over previous
#include <cuda_runtime.h>
#include <cuda_bf16.h>

#define A_N      4096
#define N_OBJ    8192
#define IN_DIM   16
#define EMBED    128
#define MAX_OBJ  16
#define DEG      8
#define OBS_DEG  8
#define POS_DIM  2
#define ORIG     18          // IN_DIM + POS_DIM
#define ORIG_P   20          // padded row stride (80B, 16B aligned)
#define OUTC     288         // MAX_OBJ * ORIG
#define NLOG     17          // MAX_OBJ + 1
#define KTOT     128         // DEG * MAX_OBJ
#define THRES    0.02f

typedef unsigned long long ull;

__device__ __forceinline__ ull f2fma(ull a, ull b, ull c) {
    ull d;
    asm("fma.rn.f32x2 %0, %1, %2, %3;" : "=l"(d) : "l"(a), "l"(b), "l"(c));
    return d;
}
__device__ __forceinline__ float f2sum(ull v) {
    float lo, hi;
    asm("mov.b64 {%0, %1}, %2;" : "=f"(lo), "=f"(hi) : "l"(v));
    return lo + hi;
}
__device__ __forceinline__ ull f2pack(float lo, float hi) {
    ull v;
    asm("mov.b64 %0, {%1, %2};" : "=l"(v) : "f"(lo), "f"(hi));
    return v;
}

// ---------------- device scratch ----------------
__device__ float  g_enc[A_N * EMBED];
// k-quad interleaved: Q[kq*cols + c] = {W[4kq][c], W[4kq+1][c], W[4kq+2][c], W[4kq+3][c]}
__device__ float4 g_mdec_WxQ[32 * OUTC];
__device__ float4 g_dec_WxQ [32 * OUTC];
__device__ float4 g_menc_W2Q[32 * EMBED];
__device__ float4 g_mdec_WsQ[32 * NLOG];
__device__ float4 g_dec_WsQ [32 * NLOG];

#define PREP_TOTAL (32 * OUTC + 32 * OUTC + 32 * EMBED + 32 * NLOG + 32 * NLOG)
#define PREP_BLOCKS ((PREP_TOTAL + 127) / 128)

__device__ __forceinline__ float4 quad(const float* __restrict__ W, int cols, int kq, int c) {
    return make_float4(W[(4 * kq    ) * cols + c], W[(4 * kq + 1) * cols + c],
                       W[(4 * kq + 2) * cols + c], W[(4 * kq + 3) * cols + c]);
}

// ---------------------------------------------------------------------------
// Kernel A (fused): blocks [0,4096) = obs encode; blocks >= 4096 = weight prep.
// ---------------------------------------------------------------------------
__global__ __launch_bounds__(128) void pre_kernel(
    const float* __restrict__ obj_x, const float* __restrict__ obj_pos,
    const float* __restrict__ agent_pos,
    const float* __restrict__ W1, const float* __restrict__ b1,
    const float* __restrict__ W2, const float* __restrict__ b2,
    const int*   __restrict__ obs_src,
    const float* __restrict__ mWx, const float* __restrict__ dWx,
    const float* __restrict__ mW2,
    const float* __restrict__ mWs, const float* __restrict__ dWs)
{
    const int t = threadIdx.x;

    if (blockIdx.x >= A_N) {
        int idx = (blockIdx.x - A_N) * 128 + t;
        if (idx < 32 * OUTC) { g_mdec_WxQ[idx] = quad(mWx, OUTC, idx / OUTC, idx % OUTC); return; }
        idx -= 32 * OUTC;
        if (idx < 32 * OUTC) { g_dec_WxQ[idx]  = quad(dWx, OUTC, idx / OUTC, idx % OUTC); return; }
        idx -= 32 * OUTC;
        if (idx < 32 * EMBED) { g_menc_W2Q[idx] = quad(mW2, EMBED, idx / EMBED, idx % EMBED); return; }
        idx -= 32 * EMBED;
        if (idx < 32 * NLOG) { g_mdec_WsQ[idx] = quad(mWs, NLOG, idx / NLOG, idx % NLOG); return; }
        idx -= 32 * NLOG;
        if (idx < 32 * NLOG) { g_dec_WsQ[idx]  = quad(dWs, NLOG, idx / NLOG, idx % NLOG); return; }
        return;
    }

    const int a = blockIdx.x;

    __shared__ __align__(16) float msg[OBS_DEG][ORIG_P];
    __shared__ __align__(16) float S[EMBED];
    __shared__ float apos[2];

    if (t < 2) apos[t] = agent_pos[2 * a + t];
    __syncthreads();

    for (int idx = t; idx < OBS_DEG * ORIG; idx += 128) {
        const int e = idx / ORIG;
        const int k = idx - e * ORIG;
        const int o = obs_src[a * OBS_DEG + e];
        float v;
        if (k < IN_DIM) v = obj_x[o * IN_DIM + k];
        else            v = obj_pos[o * POS_DIM + (k - IN_DIM)] - apos[k - IN_DIM];
        msg[e][k] = v;
    }
    __syncthreads();

    ull w1p[9];
#pragma unroll
    for (int q = 0; q < 9; q++)
        w1p[q] = f2pack(W1[(2 * q) * EMBED + t], W1[(2 * q + 1) * EMBED + t]);
    const float b1t = b1[t];

    float acc = 0.f;
#pragma unroll
    for (int e = 0; e < OBS_DEG; e++) {
        const ulonglong2* r = (const ulonglong2*)msg[e];
        ulonglong2 q0 = r[0], q1 = r[1], q2 = r[2], q3 = r[3];
        ull q4 = ((const ull*)msg[e])[8];
        ull h = 0;
        h = f2fma(q0.x, w1p[0], h); h = f2fma(q0.y, w1p[1], h);
        h = f2fma(q1.x, w1p[2], h); h = f2fma(q1.y, w1p[3], h);
        h = f2fma(q2.x, w1p[4], h); h = f2fma(q2.y, w1p[5], h);
        h = f2fma(q3.x, w1p[6], h); h = f2fma(q3.y, w1p[7], h);
        h = f2fma(q4,   w1p[8], h);
        acc += fmaxf(f2sum(h) + b1t, 0.f);
    }
    S[t] = acc;
    __syncthreads();

    float out = b2[t];
    const float4* S4 = (const float4*)S;
#pragma unroll 4
    for (int k4 = 0; k4 < EMBED / 4; k4++) {
        float4 s = S4[k4];
        const int k = 4 * k4;
        out = fmaf(s.x, W2[(k    ) * EMBED + t], out);
        out = fmaf(s.y, W2[(k + 1) * EMBED + t], out);
        out = fmaf(s.z, W2[(k + 2) * EMBED + t], out);
        out = fmaf(s.w, W2[(k + 3) * EMBED + t], out);
    }
    g_enc[a * EMBED + t] = out;
}

// ---------------------------------------------------------------------------
// Kernel B: per-agent comm decode + dedup + merge + final decode.
// ---------------------------------------------------------------------------
__global__ __launch_bounds__(128, 10) void agent_kernel(
    const float* __restrict__ agent_pos,
    const float* __restrict__ mdec_bs, const float* __restrict__ mdec_bx,
    const float* __restrict__ menc_W1, const float* __restrict__ menc_b1,
    const float* __restrict__ menc_b2,
    const float* __restrict__ dec_bs,  const float* __restrict__ dec_bx,
    const int*   __restrict__ comm_src,
    float* __restrict__ out, int write_extra)
{
    const int i = blockIdx.x;
    const int t = threadIdx.x;
    const int lane = t & 31;
    const int wrp  = t >> 5;

    __shared__ __align__(16) float zj[DEG][EMBED];       // 4 KB
    __shared__ __align__(16) float cand[KTOT][ORIG_P];   // 10 KB (aliased as dout later)
    __shared__ __align__(16) float Spre[EMBED];
    __shared__ __align__(16) float mergeds[EMBED];
    __shared__ float logitsA[DEG][NLOG], logitsB[DEG][NLOG];
    __shared__ int   npred[DEG];
    __shared__ int   keepf[KTOT];
    __shared__ float cpx[KTOT], cpy[KTOT];
    __shared__ int   cidx[KTOT];
    __shared__ float relx[DEG], rely[DEG];
    __shared__ int   jidx[DEG];
    __shared__ float dlogA[NLOG], dlogB[NLOG];
    __shared__ int   kidx[MAX_OBJ];
    __shared__ int   wtot[4], wtot2[4];
    __shared__ int   n2s;

    if (t < DEG) {
        const int j = comm_src[i * DEG + t];
        jidx[t] = j;
        relx[t] = agent_pos[2 * j    ] - agent_pos[2 * i    ];
        rely[t] = agent_pos[2 * j + 1] - agent_pos[2 * i + 1];
    }
    __syncthreads();
#pragma unroll
    for (int e = 0; e < DEG; e++) zj[e][t] = g_enc[jidx[e] * EMBED + t];
    __syncthreads();

    // ---- mdec elems: rounds 0,1 all threads; tail 32 cols split warps 0/1;
    //      logits split across warps 2/3 (half-K each) ----
    {
        const ulonglong2* WQ = (const ulonglong2*)g_mdec_WxQ;
#pragma unroll 1
        for (int ci = 0; ci < 3; ci++) {
            int c = -1;
            if (ci < 2) c = t + ci * 128;
            else if (t < 16)             c = 256 + t;          // warp0 lanes 0-15
            else if (t >= 32 && t < 48)  c = 272 + (t - 32);   // warp1 lanes 0-15
            if (c >= 0) {
                ull acc[DEG];
#pragma unroll
                for (int e = 0; e < DEG; e++) acc[e] = 0;
#pragma unroll 4
                for (int kq = 0; kq < 32; kq++) {
                    ulonglong2 w = WQ[kq * OUTC + c];
#pragma unroll
                    for (int e = 0; e < DEG; e++) {
                        ulonglong2 z = *(const ulonglong2*)&zj[e][4 * kq];
                        acc[e] = f2fma(z.x, w.x, acc[e]);
                        acc[e] = f2fma(z.y, w.y, acc[e]);
                    }
                }
                const int m = c / ORIG;
                const int dim = c - m * ORIG;
                const float bx = mdec_bx[c];
#pragma unroll
                for (int e = 0; e < DEG; e++) {
                    float v = f2sum(acc[e]) + bx;
                    if (dim == 16) v += relx[e];
                    if (dim == 17) v += rely[e];
                    cand[e * MAX_OBJ + m][dim] = v;
                }
            }
        }
        // logits: warp2 (t 64..80) does kq 0..15, warp3 (t 96..112) does kq 16..31
        if ((t >= 64 && t < 64 + NLOG) || (t >= 96 && t < 96 + NLOG)) {
            const int s = (t >= 96) ? (t - 96) : (t - 64);
            const int kq0 = (t >= 96) ? 16 : 0;
            const ulonglong2* WsQ = (const ulonglong2*)g_mdec_WsQ;
            ull acc[DEG];
#pragma unroll
            for (int e = 0; e < DEG; e++) acc[e] = 0;
#pragma unroll 4
            for (int kq = kq0; kq < kq0 + 16; kq++) {
                ulonglong2 w = WsQ[kq * NLOG + s];
#pragma unroll
                for (int e = 0; e < DEG; e++) {
                    ulonglong2 z = *(const ulonglong2*)&zj[e][4 * kq];
                    acc[e] = f2fma(z.x, w.x, acc[e]);
                    acc[e] = f2fma(z.y, w.y, acc[e]);
                }
            }
            if (t >= 96) {
#pragma unroll
                for (int e = 0; e < DEG; e++) logitsB[e][s] = f2sum(acc[e]);
            } else {
                const float bs = mdec_bs[s];
#pragma unroll
                for (int e = 0; e < DEG; e++) logitsA[e][s] = f2sum(acc[e]) + bs;
            }
        }
    }
    __syncthreads();

    // argmax per edge (first max)
    if (t < DEG) {
        float best = logitsA[t][0] + logitsB[t][0]; int bi = 0;
#pragma unroll
        for (int c = 1; c < NLOG; c++) {
            const float v = logitsA[t][c] + logitsB[t][c];
            if (v > best) { best = v; bi = c; }
        }
        npred[t] = bi;
    }
    __syncthreads();

    // ---- validity + compact + dedup ----
    const int em = t >> 4, mm = t & 15;
    const int v0 = (mm < npred[em]) ? 1 : 0;
    const float x0 = cand[t][16], y0 = cand[t][17];

    unsigned bm = __ballot_sync(0xffffffffu, v0);
    int pre = __popc(bm & ((1u << lane) - 1u));
    if (lane == 31) wtot[wrp] = pre + v0;
    keepf[t] = 0;
    __syncthreads();
    int off = 0;
#pragma unroll
    for (int q = 0; q < 4; q++) if (q < wrp) off += wtot[q];
    const int nv = wtot[0] + wtot[1] + wtot[2] + wtot[3];
    if (v0) { const int p = off + pre; cpx[p] = x0; cpy[p] = y0; cidx[p] = t; }
    __syncthreads();

    if (t < nv) {
        const float xx = cpx[t], yy = cpy[t];
        int dead = 0;
        for (int k = 0; k < t; k++) {
            const float dx = xx - cpx[k];
            const float dy = yy - cpy[k];
            if (sqrtf(fmaf(dx, dx, dy * dy)) < THRES) dead = 1;
        }
        if (!dead) keepf[cidx[t]] = 1;
    }
    __syncthreads();

    // ---- cap to 15 via prefix scan, compact kept indices ----
    const int k2 = keepf[t];
    unsigned bm2 = __ballot_sync(0xffffffffu, k2);
    int pre2 = __popc(bm2 & ((1u << lane) - 1u));
    if (lane == 31) wtot2[wrp] = pre2 + k2;
    __syncthreads();
    int off2 = 0;
#pragma unroll
    for (int q = 0; q < 4; q++) if (q < wrp) off2 += wtot2[q];
    const int tot2 = wtot2[0] + wtot2[1] + wtot2[2] + wtot2[3];
    const int ncnt = (tot2 < MAX_OBJ - 1) ? tot2 : (MAX_OBJ - 1);
    const int excl = off2 + pre2;
    if (k2 && (excl + 1 <= MAX_OBJ - 1)) kidx[excl] = t;
    __syncthreads();

    // ---- merge encode: Spre[t] = sum over kept of relu(cand . W1[:,t] + b1[t]) ----
    {
        ull w1p[9];
#pragma unroll
        for (int q = 0; q < 9; q++)
            w1p[q] = f2pack(menc_W1[(2 * q) * EMBED + t], menc_W1[(2 * q + 1) * EMBED + t]);
        const float b1t = menc_b1[t];
        float acc = 0.f;
        for (int l = 0; l < ncnt; l++) {
            const int li = kidx[l];
            const ulonglong2* r = (const ulonglong2*)cand[li];
            ulonglong2 q0 = r[0], q1 = r[1], q2 = r[2], q3 = r[3];
            ull q4 = ((const ull*)cand[li])[8];
            ull h = 0;
            h = f2fma(q0.x, w1p[0], h); h = f2fma(q0.y, w1p[1], h);
            h = f2fma(q1.x, w1p[2], h); h = f2fma(q1.y, w1p[3], h);
            h = f2fma(q2.x, w1p[4], h); h = f2fma(q2.y, w1p[5], h);
            h = f2fma(q3.x, w1p[6], h); h = f2fma(q3.y, w1p[7], h);
            h = f2fma(q4,   w1p[8], h);
            acc += fmaxf(f2sum(h) + b1t, 0.f);
        }
        Spre[t] = acc;
    }
    __syncthreads();

    // merged = Spre @ menc_W2 + b2
    {
        ull a = 0;
        const ulonglong2* WQ = (const ulonglong2*)g_menc_W2Q;
#pragma unroll 4
        for (int kq = 0; kq < 32; kq++) {
            ulonglong2 w = WQ[kq * EMBED + t];
            ulonglong2 z = *(const ulonglong2*)&Spre[4 * kq];
            a = f2fma(z.x, w.x, a);
            a = f2fma(z.y, w.y, a);
        }
        mergeds[t] = f2sum(a) + menc_b2[t];
    }
    __syncthreads();

    // ---- final decode: same split as mdec ----
    float* dout = &cand[0][0];   // cand dead now; reuse as dout[288]
    {
        const ulonglong2* WQ = (const ulonglong2*)g_dec_WxQ;
#pragma unroll 1
        for (int ci = 0; ci < 3; ci++) {
            int c = -1;
            if (ci < 2) c = t + ci * 128;
            else if (t < 16)             c = 256 + t;
            else if (t >= 32 && t < 48)  c = 272 + (t - 32);
            if (c >= 0) {
                ull a = 0;
#pragma unroll 4
                for (int kq = 0; kq < 32; kq++) {
                    ulonglong2 w = WQ[kq * OUTC + c];
                    ulonglong2 z = *(const ulonglong2*)&mergeds[4 * kq];
                    a = f2fma(z.x, w.x, a);
                    a = f2fma(z.y, w.y, a);
                }
                dout[c] = f2sum(a) + dec_bx[c];
            }
        }
        if ((t >= 64 && t < 64 + NLOG) || (t >= 96 && t < 96 + NLOG)) {
            const int s = (t >= 96) ? (t - 96) : (t - 64);
            const int kq0 = (t >= 96) ? 16 : 0;
            const ulonglong2* WsQ = (const ulonglong2*)g_dec_WsQ;
            ull a = 0;
#pragma unroll 4
            for (int kq = kq0; kq < kq0 + 16; kq++) {
                ulonglong2 w = WsQ[kq * NLOG + s];
                ulonglong2 z = *(const ulonglong2*)&mergeds[4 * kq];
                a = f2fma(z.x, w.x, a);
                a = f2fma(z.y, w.y, a);
            }
            if (t >= 96) dlogB[s] = f2sum(a);
            else         dlogA[s] = f2sum(a) + dec_bs[s];
        }
    }
    __syncthreads();
    if (t == 0) {
        float best = dlogA[0] + dlogB[0]; int bi = 0;
#pragma unroll
        for (int c = 1; c < NLOG; c++) {
            const float v = dlogA[c] + dlogB[c];
            if (v > best) { best = v; bi = c; }
        }
        n2s = bi;
    }
    __syncthreads();
    const int n2 = n2s;

    // masked writes
    {
        int c = t;
        out[(size_t)i * OUTC + c] = ((c / ORIG) < n2) ? dout[c] : 0.f;
        c = t + 128;
        out[(size_t)i * OUTC + c] = ((c / ORIG) < n2) ? dout[c] : 0.f;
        if (t < 32) {
            c = t + 256;
            out[(size_t)i * OUTC + c] = ((c / ORIG) < n2) ? dout[c] : 0.f;
        }
    }
    if (write_extra && t < MAX_OBJ) {
        const size_t batch_off = (size_t)A_N * OUTC;
        const size_t mask_off  = batch_off + (size_t)A_N * MAX_OBJ;
        out[batch_off + (size_t)i * MAX_OBJ + t] = (float)i;
        out[mask_off  + (size_t)i * MAX_OBJ + t] = (t < n2) ? 1.f : 0.f;
    }
}

extern "C" void kernel_launch(void* const* d_in, const int* in_sizes, int n_in,
                              void* d_out, int out_size) {
    const float* obj_x     = (const float*)d_in[0];
    const float* obj_pos   = (const float*)d_in[1];
    const float* agent_pos = (const float*)d_in[2];
    const float* enc_W1    = (const float*)d_in[3];
    const float* enc_b1    = (const float*)d_in[4];
    const float* enc_W2    = (const float*)d_in[5];
    const float* enc_b2    = (const float*)d_in[6];
    const float* mdec_Ws   = (const float*)d_in[7];
    const float* mdec_bs   = (const float*)d_in[8];
    const float* mdec_Wx   = (const float*)d_in[9];
    const float* mdec_bx   = (const float*)d_in[10];
    const float* menc_W1   = (const float*)d_in[11];
    const float* menc_b1   = (const float*)d_in[12];
    const float* menc_W2   = (const float*)d_in[13];
    const float* menc_b2   = (const float*)d_in[14];
    const float* dec_Ws    = (const float*)d_in[15];
    const float* dec_bs    = (const float*)d_in[16];
    const float* dec_Wx    = (const float*)d_in[17];
    const float* dec_bx    = (const float*)d_in[18];
    const int*   obs_ei    = (const int*)d_in[19];   // row0 = tgt, row1 = src
    const int*   comm_ei   = (const int*)d_in[20];   // row0 = src(j), row1 = tgt(i)

    const int* obs_src  = obs_ei  + A_N * OBS_DEG;   // row 1
    const int* comm_src = comm_ei;                   // row 0

    pre_kernel<<<A_N + PREP_BLOCKS, 128>>>(obj_x, obj_pos, agent_pos,
                                           enc_W1, enc_b1, enc_W2, enc_b2, obs_src,
                                           mdec_Wx, dec_Wx, menc_W2, mdec_Ws, dec_Ws);

    const int full = A_N * OUTC + 2 * A_N * MAX_OBJ;   // decoded + batch + mask
    const int write_extra = (out_size >= full) ? 1 : 0;

    agent_kernel<<<A_N, 128>>>(agent_pos,
                               mdec_bs, mdec_bx,
                               menc_W1, menc_b1, menc_b2,
                               dec_bs, dec_bx,
                               comm_src, (float*)d_out, write_extra);
}

// round 4
// speedup vs baseline: 1.3060x; 1.2370x over previous
#include <cuda_runtime.h>
#include <cuda_bf16.h>

#define A_N      4096
#define N_OBJ    8192
#define IN_DIM   16
#define EMBED    128
#define MAX_OBJ  16
#define DEG      8
#define OBS_DEG  8
#define POS_DIM  2
#define ORIG     18          // IN_DIM + POS_DIM
#define ORIG_P   20          // padded row stride (80B, 16B aligned)
#define OUTC     288         // MAX_OBJ * ORIG
#define NLOG     17          // MAX_OBJ + 1
#define KTOT     128         // DEG * MAX_OBJ
#define THRES    0.02f

typedef unsigned long long ull;

__device__ __forceinline__ ull f2fma(ull a, ull b, ull c) {
    ull d;
    asm("fma.rn.f32x2 %0, %1, %2, %3;" : "=l"(d) : "l"(a), "l"(b), "l"(c));
    return d;
}
__device__ __forceinline__ float f2sum(ull v) {
    float lo, hi;
    asm("mov.b64 {%0, %1}, %2;" : "=f"(lo), "=f"(hi) : "l"(v));
    return lo + hi;
}
__device__ __forceinline__ ull f2pack(float lo, float hi) {
    ull v;
    asm("mov.b64 %0, {%1, %2};" : "=l"(v) : "f"(lo), "f"(hi));
    return v;
}

// ---------------- device scratch ----------------
__device__ float  g_enc[A_N * EMBED];
// k-quad interleaved: Q[kq*cols + c] = {W[4kq][c], W[4kq+1][c], W[4kq+2][c], W[4kq+3][c]}
__device__ float4 g_mdec_WxQ[32 * OUTC];
__device__ float4 g_dec_WxQ [32 * OUTC];
__device__ float4 g_menc_W2Q[32 * EMBED];
__device__ float4 g_mdec_WsQ[32 * NLOG];
__device__ float4 g_dec_WsQ [32 * NLOG];

#define PREP_TOTAL (32 * OUTC + 32 * OUTC + 32 * EMBED + 32 * NLOG + 32 * NLOG)
#define PREP_BLOCKS ((PREP_TOTAL + 127) / 128)

__device__ __forceinline__ float4 quad(const float* __restrict__ W, int cols, int kq, int c) {
    return make_float4(W[(4 * kq    ) * cols + c], W[(4 * kq + 1) * cols + c],
                       W[(4 * kq + 2) * cols + c], W[(4 * kq + 3) * cols + c]);
}

// ---------------------------------------------------------------------------
// Kernel A (fused): blocks [0,4096) = obs encode; blocks >= 4096 = weight prep.
// ---------------------------------------------------------------------------
__global__ __launch_bounds__(128) void pre_kernel(
    const float* __restrict__ obj_x, const float* __restrict__ obj_pos,
    const float* __restrict__ agent_pos,
    const float* __restrict__ W1, const float* __restrict__ b1,
    const float* __restrict__ W2, const float* __restrict__ b2,
    const int*   __restrict__ obs_src,
    const float* __restrict__ mWx, const float* __restrict__ dWx,
    const float* __restrict__ mW2,
    const float* __restrict__ mWs, const float* __restrict__ dWs)
{
    const int t = threadIdx.x;

    if (blockIdx.x >= A_N) {
        int idx = (blockIdx.x - A_N) * 128 + t;
        if (idx < 32 * OUTC) { g_mdec_WxQ[idx] = quad(mWx, OUTC, idx / OUTC, idx % OUTC); return; }
        idx -= 32 * OUTC;
        if (idx < 32 * OUTC) { g_dec_WxQ[idx]  = quad(dWx, OUTC, idx / OUTC, idx % OUTC); return; }
        idx -= 32 * OUTC;
        if (idx < 32 * EMBED) { g_menc_W2Q[idx] = quad(mW2, EMBED, idx / EMBED, idx % EMBED); return; }
        idx -= 32 * EMBED;
        if (idx < 32 * NLOG) { g_mdec_WsQ[idx] = quad(mWs, NLOG, idx / NLOG, idx % NLOG); return; }
        idx -= 32 * NLOG;
        if (idx < 32 * NLOG) { g_dec_WsQ[idx]  = quad(dWs, NLOG, idx / NLOG, idx % NLOG); return; }
        return;
    }

    const int a = blockIdx.x;

    __shared__ __align__(16) float msg[OBS_DEG][ORIG_P];
    __shared__ __align__(16) float S[EMBED];
    __shared__ float apos[2];

    if (t < 2) apos[t] = agent_pos[2 * a + t];
    __syncthreads();

    for (int idx = t; idx < OBS_DEG * ORIG; idx += 128) {
        const int e = idx / ORIG;
        const int k = idx - e * ORIG;
        const int o = obs_src[a * OBS_DEG + e];
        float v;
        if (k < IN_DIM) v = obj_x[o * IN_DIM + k];
        else            v = obj_pos[o * POS_DIM + (k - IN_DIM)] - apos[k - IN_DIM];
        msg[e][k] = v;
    }
    __syncthreads();

    ull w1p[9];
#pragma unroll
    for (int q = 0; q < 9; q++)
        w1p[q] = f2pack(W1[(2 * q) * EMBED + t], W1[(2 * q + 1) * EMBED + t]);
    const float b1t = b1[t];

    float acc = 0.f;
#pragma unroll
    for (int e = 0; e < OBS_DEG; e++) {
        const ulonglong2* r = (const ulonglong2*)msg[e];
        ulonglong2 q0 = r[0], q1 = r[1], q2 = r[2], q3 = r[3];
        ull q4 = ((const ull*)msg[e])[8];
        ull h = 0;
        h = f2fma(q0.x, w1p[0], h); h = f2fma(q0.y, w1p[1], h);
        h = f2fma(q1.x, w1p[2], h); h = f2fma(q1.y, w1p[3], h);
        h = f2fma(q2.x, w1p[4], h); h = f2fma(q2.y, w1p[5], h);
        h = f2fma(q3.x, w1p[6], h); h = f2fma(q3.y, w1p[7], h);
        h = f2fma(q4,   w1p[8], h);
        acc += fmaxf(f2sum(h) + b1t, 0.f);
    }
    S[t] = acc;
    __syncthreads();

    float out = b2[t];
    const float4* S4 = (const float4*)S;
#pragma unroll 4
    for (int k4 = 0; k4 < EMBED / 4; k4++) {
        float4 s = S4[k4];
        const int k = 4 * k4;
        out = fmaf(s.x, W2[(k    ) * EMBED + t], out);
        out = fmaf(s.y, W2[(k + 1) * EMBED + t], out);
        out = fmaf(s.z, W2[(k + 2) * EMBED + t], out);
        out = fmaf(s.w, W2[(k + 3) * EMBED + t], out);
    }
    g_enc[a * EMBED + t] = out;
}

// ---------------------------------------------------------------------------
// Kernel B: per-agent comm decode + dedup + merge + final decode.
// NCOL=2 register tiling on the main GEMV passes; split-K tail.
// ---------------------------------------------------------------------------
__global__ __launch_bounds__(128, 6) void agent_kernel(
    const float* __restrict__ agent_pos,
    const float* __restrict__ mdec_bs, const float* __restrict__ mdec_bx,
    const float* __restrict__ menc_W1, const float* __restrict__ menc_b1,
    const float* __restrict__ menc_b2,
    const float* __restrict__ dec_bs,  const float* __restrict__ dec_bx,
    const int*   __restrict__ comm_src,
    float* __restrict__ out, int write_extra)
{
    const int i = blockIdx.x;
    const int t = threadIdx.x;
    const int lane = t & 31;
    const int wrp  = t >> 5;

    __shared__ __align__(16) float zj[DEG][EMBED];       // 4 KB
    __shared__ __align__(16) float cand[KTOT][ORIG_P];   // 10 KB (aliased as dout later)
    __shared__ __align__(16) float Spre[EMBED];
    __shared__ __align__(16) float mergeds[EMBED];
    __shared__ float psA[32][DEG], psB[32][DEG];         // split-K partials (tail elems)
    __shared__ float logitsA[DEG][NLOG], logitsB[DEG][NLOG];
    __shared__ int   npred[DEG];
    __shared__ int   keepf[KTOT];
    __shared__ float cpx[KTOT], cpy[KTOT];
    __shared__ int   cidx[KTOT];
    __shared__ float relx[DEG], rely[DEG];
    __shared__ int   jidx[DEG];
    __shared__ float dlogA[NLOG], dlogB[NLOG];
    __shared__ int   kidx[MAX_OBJ];
    __shared__ int   wtot[4], wtot2[4];
    __shared__ int   n2s;

    if (t < DEG) {
        const int j = comm_src[i * DEG + t];
        jidx[t] = j;
        relx[t] = agent_pos[2 * j    ] - agent_pos[2 * i    ];
        rely[t] = agent_pos[2 * j + 1] - agent_pos[2 * i + 1];
    }
    __syncthreads();
#pragma unroll
    for (int e = 0; e < DEG; e++) zj[e][t] = g_enc[jidx[e] * EMBED + t];
    __syncthreads();

    // ================= mdec: main pass, cols {t, t+128}, all 8 edges =========
    {
        const ulonglong2* WQ = (const ulonglong2*)g_mdec_WxQ;
        ull acc0[DEG], acc1[DEG];
#pragma unroll
        for (int e = 0; e < DEG; e++) { acc0[e] = 0; acc1[e] = 0; }
#pragma unroll 2
        for (int kq = 0; kq < 32; kq++) {
            ulonglong2 w0 = WQ[kq * OUTC + t];
            ulonglong2 w1 = WQ[kq * OUTC + t + 128];
#pragma unroll
            for (int e = 0; e < DEG; e++) {
                ulonglong2 z = *(const ulonglong2*)&zj[e][4 * kq];
                acc0[e] = f2fma(z.x, w0.x, acc0[e]);
                acc0[e] = f2fma(z.y, w0.y, acc0[e]);
                acc1[e] = f2fma(z.x, w1.x, acc1[e]);
                acc1[e] = f2fma(z.y, w1.y, acc1[e]);
            }
        }
        {
            const int c = t, m = c / ORIG, dim = c - m * ORIG;
            const float bx = mdec_bx[c];
#pragma unroll
            for (int e = 0; e < DEG; e++) {
                float v = f2sum(acc0[e]) + bx;
                if (dim == 16) v += relx[e];
                if (dim == 17) v += rely[e];
                cand[e * MAX_OBJ + m][dim] = v;
            }
        }
        {
            const int c = t + 128, m = c / ORIG, dim = c - m * ORIG;
            const float bx = mdec_bx[c];
#pragma unroll
            for (int e = 0; e < DEG; e++) {
                float v = f2sum(acc1[e]) + bx;
                if (dim == 16) v += relx[e];
                if (dim == 17) v += rely[e];
                cand[e * MAX_OBJ + m][dim] = v;
            }
        }
    }
    // ================= mdec: tail (cols 256..287 + 17 logits), split-K =======
    {
        const int kq0 = (wrp & 1) ? 16 : 0;
        if (wrp < 2) {
            // elem col 256+lane, half-K
            const int c = 256 + lane;
            const ulonglong2* WQ = (const ulonglong2*)g_mdec_WxQ;
            ull acc[DEG];
#pragma unroll
            for (int e = 0; e < DEG; e++) acc[e] = 0;
#pragma unroll 4
            for (int kq = kq0; kq < kq0 + 16; kq++) {
                ulonglong2 w = WQ[kq * OUTC + c];
#pragma unroll
                for (int e = 0; e < DEG; e++) {
                    ulonglong2 z = *(const ulonglong2*)&zj[e][4 * kq];
                    acc[e] = f2fma(z.x, w.x, acc[e]);
                    acc[e] = f2fma(z.y, w.y, acc[e]);
                }
            }
            if (wrp == 0) {
#pragma unroll
                for (int e = 0; e < DEG; e++) psA[lane][e] = f2sum(acc[e]);
            } else {
#pragma unroll
                for (int e = 0; e < DEG; e++) psB[lane][e] = f2sum(acc[e]);
            }
        } else if (lane < NLOG) {
            const int s = lane;
            const ulonglong2* WsQ = (const ulonglong2*)g_mdec_WsQ;
            ull acc[DEG];
#pragma unroll
            for (int e = 0; e < DEG; e++) acc[e] = 0;
#pragma unroll 4
            for (int kq = kq0; kq < kq0 + 16; kq++) {
                ulonglong2 w = WsQ[kq * NLOG + s];
#pragma unroll
                for (int e = 0; e < DEG; e++) {
                    ulonglong2 z = *(const ulonglong2*)&zj[e][4 * kq];
                    acc[e] = f2fma(z.x, w.x, acc[e]);
                    acc[e] = f2fma(z.y, w.y, acc[e]);
                }
            }
            if (wrp == 2) {
                const float bs = mdec_bs[s];
#pragma unroll
                for (int e = 0; e < DEG; e++) logitsA[e][s] = f2sum(acc[e]) + bs;
            } else {
#pragma unroll
                for (int e = 0; e < DEG; e++) logitsB[e][s] = f2sum(acc[e]);
            }
        }
    }
    __syncthreads();

    // combine tail elems (256 (col,e) pairs over 128 threads) + argmax per edge
#pragma unroll
    for (int r = 0; r < 2; r++) {
        const int p = t + r * 128;
        const int cl = p >> 3;            // 0..31
        const int e  = p & 7;
        const int c  = 256 + cl;
        const int m = c / ORIG, dim = c - m * ORIG;
        float v = psA[cl][e] + psB[cl][e] + mdec_bx[c];
        if (dim == 16) v += relx[e];
        if (dim == 17) v += rely[e];
        cand[e * MAX_OBJ + m][dim] = v;
    }
    if (t < DEG) {
        float best = logitsA[t][0] + logitsB[t][0]; int bi = 0;
#pragma unroll
        for (int c = 1; c < NLOG; c++) {
            const float v = logitsA[t][c] + logitsB[t][c];
            if (v > best) { best = v; bi = c; }
        }
        npred[t] = bi;
    }
    __syncthreads();

    // ---- validity + compact + dedup ----
    const int em = t >> 4, mm = t & 15;
    const int v0 = (mm < npred[em]) ? 1 : 0;
    const float x0 = cand[t][16], y0 = cand[t][17];

    unsigned bm = __ballot_sync(0xffffffffu, v0);
    int pre = __popc(bm & ((1u << lane) - 1u));
    if (lane == 31) wtot[wrp] = pre + v0;
    keepf[t] = 0;
    __syncthreads();
    int off = 0;
#pragma unroll
    for (int q = 0; q < 4; q++) if (q < wrp) off += wtot[q];
    const int nv = wtot[0] + wtot[1] + wtot[2] + wtot[3];
    if (v0) { const int p = off + pre; cpx[p] = x0; cpy[p] = y0; cidx[p] = t; }
    __syncthreads();

    if (t < nv) {
        const float xx = cpx[t], yy = cpy[t];
        int dead = 0;
        for (int k = 0; k < t; k++) {
            const float dx = xx - cpx[k];
            const float dy = yy - cpy[k];
            if (sqrtf(fmaf(dx, dx, dy * dy)) < THRES) dead = 1;
        }
        if (!dead) keepf[cidx[t]] = 1;
    }
    __syncthreads();

    // ---- cap to 15 via prefix scan, compact kept indices ----
    const int k2 = keepf[t];
    unsigned bm2 = __ballot_sync(0xffffffffu, k2);
    int pre2 = __popc(bm2 & ((1u << lane) - 1u));
    if (lane == 31) wtot2[wrp] = pre2 + k2;
    __syncthreads();
    int off2 = 0;
#pragma unroll
    for (int q = 0; q < 4; q++) if (q < wrp) off2 += wtot2[q];
    const int tot2 = wtot2[0] + wtot2[1] + wtot2[2] + wtot2[3];
    const int ncnt = (tot2 < MAX_OBJ - 1) ? tot2 : (MAX_OBJ - 1);
    const int excl = off2 + pre2;
    if (k2 && (excl + 1 <= MAX_OBJ - 1)) kidx[excl] = t;
    __syncthreads();

    // ---- merge encode: Spre[t] = sum over kept of relu(cand . W1[:,t] + b1[t]) ----
    {
        ull w1p[9];
#pragma unroll
        for (int q = 0; q < 9; q++)
            w1p[q] = f2pack(menc_W1[(2 * q) * EMBED + t], menc_W1[(2 * q + 1) * EMBED + t]);
        const float b1t = menc_b1[t];
        float acc = 0.f;
        for (int l = 0; l < ncnt; l++) {
            const int li = kidx[l];
            const ulonglong2* r = (const ulonglong2*)cand[li];
            ulonglong2 q0 = r[0], q1 = r[1], q2 = r[2], q3 = r[3];
            ull q4 = ((const ull*)cand[li])[8];
            ull h = 0;
            h = f2fma(q0.x, w1p[0], h); h = f2fma(q0.y, w1p[1], h);
            h = f2fma(q1.x, w1p[2], h); h = f2fma(q1.y, w1p[3], h);
            h = f2fma(q2.x, w1p[4], h); h = f2fma(q2.y, w1p[5], h);
            h = f2fma(q3.x, w1p[6], h); h = f2fma(q3.y, w1p[7], h);
            h = f2fma(q4,   w1p[8], h);
            acc += fmaxf(f2sum(h) + b1t, 0.f);
        }
        Spre[t] = acc;
    }
    __syncthreads();

    // merged = Spre @ menc_W2 + b2
    {
        ull a = 0;
        const ulonglong2* WQ = (const ulonglong2*)g_menc_W2Q;
#pragma unroll 4
        for (int kq = 0; kq < 32; kq++) {
            ulonglong2 w = WQ[kq * EMBED + t];
            ulonglong2 z = *(const ulonglong2*)&Spre[4 * kq];
            a = f2fma(z.x, w.x, a);
            a = f2fma(z.y, w.y, a);
        }
        mergeds[t] = f2sum(a) + menc_b2[t];
    }
    __syncthreads();

    // ================= final decode: main pass cols {t, t+128} ===============
    float* dout = &cand[0][0];   // cand dead now; reuse as dout[288]
    {
        const ulonglong2* WQ = (const ulonglong2*)g_dec_WxQ;
        ull a0 = 0, a1 = 0;
#pragma unroll 4
        for (int kq = 0; kq < 32; kq++) {
            ulonglong2 w0 = WQ[kq * OUTC + t];
            ulonglong2 w1 = WQ[kq * OUTC + t + 128];
            ulonglong2 z = *(const ulonglong2*)&mergeds[4 * kq];
            a0 = f2fma(z.x, w0.x, a0);
            a0 = f2fma(z.y, w0.y, a0);
            a1 = f2fma(z.x, w1.x, a1);
            a1 = f2fma(z.y, w1.y, a1);
        }
        dout[t]       = f2sum(a0) + dec_bx[t];
        dout[t + 128] = f2sum(a1) + dec_bx[t + 128];
    }
    // tail: cols 256..287 split-K on warps 0/1; dec logits split-K on warps 2/3
    {
        const int kq0 = (wrp & 1) ? 16 : 0;
        if (wrp < 2) {
            const int c = 256 + lane;
            const ulonglong2* WQ = (const ulonglong2*)g_dec_WxQ;
            ull a = 0;
#pragma unroll 4
            for (int kq = kq0; kq < kq0 + 16; kq++) {
                ulonglong2 w = WQ[kq * OUTC + c];
                ulonglong2 z = *(const ulonglong2*)&mergeds[4 * kq];
                a = f2fma(z.x, w.x, a);
                a = f2fma(z.y, w.y, a);
            }
            if (wrp == 0) psA[lane][0] = f2sum(a);
            else          psB[lane][0] = f2sum(a);
        } else if (lane < NLOG) {
            const int s = lane;
            const ulonglong2* WsQ = (const ulonglong2*)g_dec_WsQ;
            ull a = 0;
#pragma unroll 4
            for (int kq = kq0; kq < kq0 + 16; kq++) {
                ulonglong2 w = WsQ[kq * NLOG + s];
                ulonglong2 z = *(const ulonglong2*)&mergeds[4 * kq];
                a = f2fma(z.x, w.x, a);
                a = f2fma(z.y, w.y, a);
            }
            if (wrp == 2) dlogA[s] = f2sum(a) + dec_bs[s];
            else          dlogB[s] = f2sum(a);
        }
    }
    __syncthreads();
    if (t == 0) {
        float best = dlogA[0] + dlogB[0]; int bi = 0;
#pragma unroll
        for (int c = 1; c < NLOG; c++) {
            const float v = dlogA[c] + dlogB[c];
            if (v > best) { best = v; bi = c; }
        }
        n2s = bi;
    }
    if (t < 32) dout[256 + t] = psA[t][0] + psB[t][0] + dec_bx[256 + t];
    __syncthreads();
    const int n2 = n2s;

    // masked writes
    {
        int c = t;
        out[(size_t)i * OUTC + c] = ((c / ORIG) < n2) ? dout[c] : 0.f;
        c = t + 128;
        out[(size_t)i * OUTC + c] = ((c / ORIG) < n2) ? dout[c] : 0.f;
        if (t < 32) {
            c = t + 256;
            out[(size_t)i * OUTC + c] = ((c / ORIG) < n2) ? dout[c] : 0.f;
        }
    }
    if (write_extra && t < MAX_OBJ) {
        const size_t batch_off = (size_t)A_N * OUTC;
        const size_t mask_off  = batch_off + (size_t)A_N * MAX_OBJ;
        out[batch_off + (size_t)i * MAX_OBJ + t] = (float)i;
        out[mask_off  + (size_t)i * MAX_OBJ + t] = (t < n2) ? 1.f : 0.f;
    }
}

extern "C" void kernel_launch(void* const* d_in, const int* in_sizes, int n_in,
                              void* d_out, int out_size) {
    const float* obj_x     = (const float*)d_in[0];
    const float* obj_pos   = (const float*)d_in[1];
    const float* agent_pos = (const float*)d_in[2];
    const float* enc_W1    = (const float*)d_in[3];
    const float* enc_b1    = (const float*)d_in[4];
    const float* enc_W2    = (const float*)d_in[5];
    const float* enc_b2    = (const float*)d_in[6];
    const float* mdec_Ws   = (const float*)d_in[7];
    const float* mdec_bs   = (const float*)d_in[8];
    const float* mdec_Wx   = (const float*)d_in[9];
    const float* mdec_bx   = (const float*)d_in[10];
    const float* menc_W1   = (const float*)d_in[11];
    const float* menc_b1   = (const float*)d_in[12];
    const float* menc_W2   = (const float*)d_in[13];
    const float* menc_b2   = (const float*)d_in[14];
    const float* dec_Ws    = (const float*)d_in[15];
    const float* dec_bs    = (const float*)d_in[16];
    const float* dec_Wx    = (const float*)d_in[17];
    const float* dec_bx    = (const float*)d_in[18];
    const int*   obs_ei    = (const int*)d_in[19];   // row0 = tgt, row1 = src
    const int*   comm_ei   = (const int*)d_in[20];   // row0 = src(j), row1 = tgt(i)

    const int* obs_src  = obs_ei  + A_N * OBS_DEG;   // row 1
    const int* comm_src = comm_ei;                   // row 0

    pre_kernel<<<A_N + PREP_BLOCKS, 128>>>(obj_x, obj_pos, agent_pos,
                                           enc_W1, enc_b1, enc_W2, enc_b2, obs_src,
                                           mdec_Wx, dec_Wx, menc_W2, mdec_Ws, dec_Ws);

    const int full = A_N * OUTC + 2 * A_N * MAX_OBJ;   // decoded + batch + mask
    const int write_extra = (out_size >= full) ? 1 : 0;

    agent_kernel<<<A_N, 128>>>(agent_pos,
                               mdec_bs, mdec_bx,
                               menc_W1, menc_b1, menc_b2,
                               dec_bs, dec_bx,
                               comm_src, (float*)d_out, write_extra);
}

// round 5
// speedup vs baseline: 1.9792x; 1.5155x over previous
#include <cuda_runtime.h>
#include <cuda_bf16.h>

#define A_N      4096
#define N_OBJ    8192
#define IN_DIM   16
#define EMBED    128
#define MAX_OBJ  16
#define DEG      8
#define OBS_DEG  8
#define POS_DIM  2
#define ORIG     18          // IN_DIM + POS_DIM
#define ORIG_P   20          // padded row stride (80B, 16B aligned)
#define OUTC     288         // MAX_OBJ * ORIG
#define NLOG     17          // MAX_OBJ + 1
#define KTOT     128         // DEG * MAX_OBJ
#define THRES    0.02f

typedef unsigned long long ull;

__device__ __forceinline__ ull f2fma(ull a, ull b, ull c) {
    ull d;
    asm("fma.rn.f32x2 %0, %1, %2, %3;" : "=l"(d) : "l"(a), "l"(b), "l"(c));
    return d;
}
__device__ __forceinline__ float f2sum(ull v) {
    float lo, hi;
    asm("mov.b64 {%0, %1}, %2;" : "=f"(lo), "=f"(hi) : "l"(v));
    return lo + hi;
}
__device__ __forceinline__ ull f2pack(float lo, float hi) {
    ull v;
    asm("mov.b64 %0, {%1, %2};" : "=l"(v) : "f"(lo), "f"(hi));
    return v;
}

// ---------------- device scratch ----------------
__device__ float  g_enc[A_N * EMBED];
__device__ float  g_elems0[A_N * OUTC];    // per-source decoded elems (pre relpos)
__device__ int    g_npred[A_N];            // per-source argmax count
// k-quad interleaved: Q[kq*cols + c] = {W[4kq][c], W[4kq+1][c], W[4kq+2][c], W[4kq+3][c]}
__device__ float4 g_mdec_WxQ[32 * OUTC];
__device__ float4 g_dec_WxQ [32 * OUTC];
__device__ float4 g_menc_W2Q[32 * EMBED];
__device__ float4 g_mdec_WsQ[32 * NLOG];
__device__ float4 g_dec_WsQ [32 * NLOG];

#define PREP_TOTAL (32 * OUTC + 32 * OUTC + 32 * EMBED + 32 * NLOG + 32 * NLOG)
#define PREP_BLOCKS ((PREP_TOTAL + 127) / 128)

__device__ __forceinline__ float4 quad(const float* __restrict__ W, int cols, int kq, int c) {
    return make_float4(W[(4 * kq    ) * cols + c], W[(4 * kq + 1) * cols + c],
                       W[(4 * kq + 2) * cols + c], W[(4 * kq + 3) * cols + c]);
}

// ---------------------------------------------------------------------------
// Kernel A (fused): blocks [0,4096) = obs encode; blocks >= 4096 = weight prep.
// ---------------------------------------------------------------------------
__global__ __launch_bounds__(128) void pre_kernel(
    const float* __restrict__ obj_x, const float* __restrict__ obj_pos,
    const float* __restrict__ agent_pos,
    const float* __restrict__ W1, const float* __restrict__ b1,
    const float* __restrict__ W2, const float* __restrict__ b2,
    const int*   __restrict__ obs_src,
    const float* __restrict__ mWx, const float* __restrict__ dWx,
    const float* __restrict__ mW2,
    const float* __restrict__ mWs, const float* __restrict__ dWs)
{
    const int t = threadIdx.x;

    if (blockIdx.x >= A_N) {
        int idx = (blockIdx.x - A_N) * 128 + t;
        if (idx < 32 * OUTC) { g_mdec_WxQ[idx] = quad(mWx, OUTC, idx / OUTC, idx % OUTC); return; }
        idx -= 32 * OUTC;
        if (idx < 32 * OUTC) { g_dec_WxQ[idx]  = quad(dWx, OUTC, idx / OUTC, idx % OUTC); return; }
        idx -= 32 * OUTC;
        if (idx < 32 * EMBED) { g_menc_W2Q[idx] = quad(mW2, EMBED, idx / EMBED, idx % EMBED); return; }
        idx -= 32 * EMBED;
        if (idx < 32 * NLOG) { g_mdec_WsQ[idx] = quad(mWs, NLOG, idx / NLOG, idx % NLOG); return; }
        idx -= 32 * NLOG;
        if (idx < 32 * NLOG) { g_dec_WsQ[idx]  = quad(dWs, NLOG, idx / NLOG, idx % NLOG); return; }
        return;
    }

    const int a = blockIdx.x;

    __shared__ __align__(16) float msg[OBS_DEG][ORIG_P];
    __shared__ __align__(16) float S[EMBED];
    __shared__ float apos[2];

    if (t < 2) apos[t] = agent_pos[2 * a + t];
    __syncthreads();

    for (int idx = t; idx < OBS_DEG * ORIG; idx += 128) {
        const int e = idx / ORIG;
        const int k = idx - e * ORIG;
        const int o = obs_src[a * OBS_DEG + e];
        float v;
        if (k < IN_DIM) v = obj_x[o * IN_DIM + k];
        else            v = obj_pos[o * POS_DIM + (k - IN_DIM)] - apos[k - IN_DIM];
        msg[e][k] = v;
    }
    __syncthreads();

    ull w1p[9];
#pragma unroll
    for (int q = 0; q < 9; q++)
        w1p[q] = f2pack(W1[(2 * q) * EMBED + t], W1[(2 * q + 1) * EMBED + t]);
    const float b1t = b1[t];

    float acc = 0.f;
#pragma unroll
    for (int e = 0; e < OBS_DEG; e++) {
        const ulonglong2* r = (const ulonglong2*)msg[e];
        ulonglong2 q0 = r[0], q1 = r[1], q2 = r[2], q3 = r[3];
        ull q4 = ((const ull*)msg[e])[8];
        ull h = 0;
        h = f2fma(q0.x, w1p[0], h); h = f2fma(q0.y, w1p[1], h);
        h = f2fma(q1.x, w1p[2], h); h = f2fma(q1.y, w1p[3], h);
        h = f2fma(q2.x, w1p[4], h); h = f2fma(q2.y, w1p[5], h);
        h = f2fma(q3.x, w1p[6], h); h = f2fma(q3.y, w1p[7], h);
        h = f2fma(q4,   w1p[8], h);
        acc += fmaxf(f2sum(h) + b1t, 0.f);
    }
    S[t] = acc;
    __syncthreads();

    float out = b2[t];
    const float4* S4 = (const float4*)S;
#pragma unroll 4
    for (int k4 = 0; k4 < EMBED / 4; k4++) {
        float4 s = S4[k4];
        const int k = 4 * k4;
        out = fmaf(s.x, W2[(k    ) * EMBED + t], out);
        out = fmaf(s.y, W2[(k + 1) * EMBED + t], out);
        out = fmaf(s.z, W2[(k + 2) * EMBED + t], out);
        out = fmaf(s.w, W2[(k + 3) * EMBED + t], out);
    }
    g_enc[a * EMBED + t] = out;
}

// ---------------------------------------------------------------------------
// Kernel A2: per-SOURCE mdec decode, batch 8 agents per block (runs ONCE per
// agent instead of once per edge -> 8x less work than doing it in agent_kernel).
// elems0[j] = g_enc[j] @ mdec_Wx + bx ;  npred[j] = argmax(g_enc[j] @ mdec_Ws + bs)
// ---------------------------------------------------------------------------
__global__ __launch_bounds__(128) void mdec_kernel(
    const float* __restrict__ mdec_bs, const float* __restrict__ mdec_bx)
{
    const int j0 = blockIdx.x * 8;
    const int t = threadIdx.x;
    const int lane = t & 31;
    const int wrp  = t >> 5;

    __shared__ __align__(16) float zj[DEG][EMBED];
    __shared__ float psA[32][DEG], psB[32][DEG];
    __shared__ float logitsA[DEG][NLOG], logitsB[DEG][NLOG];

#pragma unroll
    for (int e = 0; e < DEG; e++) zj[e][t] = g_enc[(j0 + e) * EMBED + t];
    __syncthreads();

    // main pass: cols {t, t+128} for all 8 agents
    {
        const ulonglong2* WQ = (const ulonglong2*)g_mdec_WxQ;
        ull acc0[DEG], acc1[DEG];
#pragma unroll
        for (int e = 0; e < DEG; e++) { acc0[e] = 0; acc1[e] = 0; }
#pragma unroll 2
        for (int kq = 0; kq < 32; kq++) {
            ulonglong2 w0 = WQ[kq * OUTC + t];
            ulonglong2 w1 = WQ[kq * OUTC + t + 128];
#pragma unroll
            for (int e = 0; e < DEG; e++) {
                ulonglong2 z = *(const ulonglong2*)&zj[e][4 * kq];
                acc0[e] = f2fma(z.x, w0.x, acc0[e]);
                acc0[e] = f2fma(z.y, w0.y, acc0[e]);
                acc1[e] = f2fma(z.x, w1.x, acc1[e]);
                acc1[e] = f2fma(z.y, w1.y, acc1[e]);
            }
        }
        const float bx0 = mdec_bx[t];
        const float bx1 = mdec_bx[t + 128];
#pragma unroll
        for (int e = 0; e < DEG; e++) {
            g_elems0[(j0 + e) * OUTC + t]       = f2sum(acc0[e]) + bx0;
            g_elems0[(j0 + e) * OUTC + t + 128] = f2sum(acc1[e]) + bx1;
        }
    }
    // tail: cols 256..287 split-K warps 0/1; logits split-K warps 2/3
    {
        const int kq0 = (wrp & 1) ? 16 : 0;
        if (wrp < 2) {
            const int c = 256 + lane;
            const ulonglong2* WQ = (const ulonglong2*)g_mdec_WxQ;
            ull acc[DEG];
#pragma unroll
            for (int e = 0; e < DEG; e++) acc[e] = 0;
#pragma unroll 4
            for (int kq = kq0; kq < kq0 + 16; kq++) {
                ulonglong2 w = WQ[kq * OUTC + c];
#pragma unroll
                for (int e = 0; e < DEG; e++) {
                    ulonglong2 z = *(const ulonglong2*)&zj[e][4 * kq];
                    acc[e] = f2fma(z.x, w.x, acc[e]);
                    acc[e] = f2fma(z.y, w.y, acc[e]);
                }
            }
            if (wrp == 0) {
#pragma unroll
                for (int e = 0; e < DEG; e++) psA[lane][e] = f2sum(acc[e]);
            } else {
#pragma unroll
                for (int e = 0; e < DEG; e++) psB[lane][e] = f2sum(acc[e]);
            }
        } else if (lane < NLOG) {
            const int s = lane;
            const ulonglong2* WsQ = (const ulonglong2*)g_mdec_WsQ;
            ull acc[DEG];
#pragma unroll
            for (int e = 0; e < DEG; e++) acc[e] = 0;
#pragma unroll 4
            for (int kq = kq0; kq < kq0 + 16; kq++) {
                ulonglong2 w = WsQ[kq * NLOG + s];
#pragma unroll
                for (int e = 0; e < DEG; e++) {
                    ulonglong2 z = *(const ulonglong2*)&zj[e][4 * kq];
                    acc[e] = f2fma(z.x, w.x, acc[e]);
                    acc[e] = f2fma(z.y, w.y, acc[e]);
                }
            }
            if (wrp == 2) {
                const float bs = mdec_bs[s];
#pragma unroll
                for (int e = 0; e < DEG; e++) logitsA[e][s] = f2sum(acc[e]) + bs;
            } else {
#pragma unroll
                for (int e = 0; e < DEG; e++) logitsB[e][s] = f2sum(acc[e]);
            }
        }
    }
    __syncthreads();

    // combine tail elems + argmax
#pragma unroll
    for (int r = 0; r < 2; r++) {
        const int p = t + r * 128;
        const int cl = p >> 3;            // 0..31
        const int e  = p & 7;
        const int c  = 256 + cl;
        g_elems0[(j0 + e) * OUTC + c] = psA[cl][e] + psB[cl][e] + mdec_bx[c];
    }
    if (t < DEG) {
        float best = logitsA[t][0] + logitsB[t][0]; int bi = 0;
#pragma unroll
        for (int c = 1; c < NLOG; c++) {
            const float v = logitsA[t][c] + logitsB[t][c];
            if (v > best) { best = v; bi = c; }
        }
        g_npred[j0 + t] = bi;
    }
}

// ---------------------------------------------------------------------------
// Kernel B: per-agent gather + dedup + merge + final decode.
// ---------------------------------------------------------------------------
__global__ __launch_bounds__(128, 8) void agent_kernel(
    const float* __restrict__ agent_pos,
    const float* __restrict__ menc_W1, const float* __restrict__ menc_b1,
    const float* __restrict__ menc_b2,
    const float* __restrict__ dec_bs,  const float* __restrict__ dec_bx,
    const int*   __restrict__ comm_src,
    float* __restrict__ out, int write_extra)
{
    const int i = blockIdx.x;
    const int t = threadIdx.x;
    const int lane = t & 31;
    const int wrp  = t >> 5;

    __shared__ __align__(16) float cand[KTOT][ORIG_P];   // 10 KB (aliased as dout later)
    __shared__ __align__(16) float Spre[EMBED];
    __shared__ __align__(16) float mergeds[EMBED];
    __shared__ float psA[32], psB[32];
    __shared__ int   npred[DEG];
    __shared__ int   keepf[KTOT];
    __shared__ float cpx[KTOT], cpy[KTOT];
    __shared__ int   cidx[KTOT];
    __shared__ float relx[DEG], rely[DEG];
    __shared__ int   jidx[DEG];
    __shared__ float dlogA[NLOG], dlogB[NLOG];
    __shared__ int   kidx[MAX_OBJ];
    __shared__ int   wtot[4], wtot2[4];
    __shared__ int   n2s;

    if (t < DEG) {
        const int j = comm_src[i * DEG + t];
        jidx[t] = j;
        relx[t] = agent_pos[2 * j    ] - agent_pos[2 * i    ];
        rely[t] = agent_pos[2 * j + 1] - agent_pos[2 * i + 1];
        npred[t] = g_npred[j];
    }
    __syncthreads();

    // ---- gather cand from precomputed elems0, adding relpos on dims 16/17 ----
#pragma unroll
    for (int e = 0; e < DEG; e++) {
        const float* src = &g_elems0[jidx[e] * OUTC];
        const float rx = relx[e], ry = rely[e];
        {
            const int c = t, m = c / ORIG, dim = c - m * ORIG;
            float v = src[c];
            if (dim == 16) v += rx;
            if (dim == 17) v += ry;
            cand[e * MAX_OBJ + m][dim] = v;
        }
        {
            const int c = t + 128, m = c / ORIG, dim = c - m * ORIG;
            float v = src[c];
            if (dim == 16) v += rx;
            if (dim == 17) v += ry;
            cand[e * MAX_OBJ + m][dim] = v;
        }
        if (t < 32) {
            const int c = t + 256, m = c / ORIG, dim = c - m * ORIG;
            float v = src[c];
            if (dim == 16) v += rx;
            if (dim == 17) v += ry;
            cand[e * MAX_OBJ + m][dim] = v;
        }
    }
    __syncthreads();

    // ---- validity + compact + dedup ----
    const int em = t >> 4, mm = t & 15;
    const int v0 = (mm < npred[em]) ? 1 : 0;
    const float x0 = cand[t][16], y0 = cand[t][17];

    unsigned bm = __ballot_sync(0xffffffffu, v0);
    int pre = __popc(bm & ((1u << lane) - 1u));
    if (lane == 31) wtot[wrp] = pre + v0;
    keepf[t] = 0;
    __syncthreads();
    int off = 0;
#pragma unroll
    for (int q = 0; q < 4; q++) if (q < wrp) off += wtot[q];
    const int nv = wtot[0] + wtot[1] + wtot[2] + wtot[3];
    if (v0) { const int p = off + pre; cpx[p] = x0; cpy[p] = y0; cidx[p] = t; }
    __syncthreads();

    if (t < nv) {
        const float xx = cpx[t], yy = cpy[t];
        int dead = 0;
        for (int k = 0; k < t; k++) {
            const float dx = xx - cpx[k];
            const float dy = yy - cpy[k];
            if (sqrtf(fmaf(dx, dx, dy * dy)) < THRES) dead = 1;
        }
        if (!dead) keepf[cidx[t]] = 1;
    }
    __syncthreads();

    // ---- cap to 15 via prefix scan, compact kept indices ----
    const int k2 = keepf[t];
    unsigned bm2 = __ballot_sync(0xffffffffu, k2);
    int pre2 = __popc(bm2 & ((1u << lane) - 1u));
    if (lane == 31) wtot2[wrp] = pre2 + k2;
    __syncthreads();
    int off2 = 0;
#pragma unroll
    for (int q = 0; q < 4; q++) if (q < wrp) off2 += wtot2[q];
    const int tot2 = wtot2[0] + wtot2[1] + wtot2[2] + wtot2[3];
    const int ncnt = (tot2 < MAX_OBJ - 1) ? tot2 : (MAX_OBJ - 1);
    const int excl = off2 + pre2;
    if (k2 && (excl + 1 <= MAX_OBJ - 1)) kidx[excl] = t;
    __syncthreads();

    // ---- merge encode: Spre[t] = sum over kept of relu(cand . W1[:,t] + b1[t]) ----
    {
        ull w1p[9];
#pragma unroll
        for (int q = 0; q < 9; q++)
            w1p[q] = f2pack(menc_W1[(2 * q) * EMBED + t], menc_W1[(2 * q + 1) * EMBED + t]);
        const float b1t = menc_b1[t];
        float acc = 0.f;
        for (int l = 0; l < ncnt; l++) {
            const int li = kidx[l];
            const ulonglong2* r = (const ulonglong2*)cand[li];
            ulonglong2 q0 = r[0], q1 = r[1], q2 = r[2], q3 = r[3];
            ull q4 = ((const ull*)cand[li])[8];
            ull h = 0;
            h = f2fma(q0.x, w1p[0], h); h = f2fma(q0.y, w1p[1], h);
            h = f2fma(q1.x, w1p[2], h); h = f2fma(q1.y, w1p[3], h);
            h = f2fma(q2.x, w1p[4], h); h = f2fma(q2.y, w1p[5], h);
            h = f2fma(q3.x, w1p[6], h); h = f2fma(q3.y, w1p[7], h);
            h = f2fma(q4,   w1p[8], h);
            acc += fmaxf(f2sum(h) + b1t, 0.f);
        }
        Spre[t] = acc;
    }
    __syncthreads();

    // merged = Spre @ menc_W2 + b2
    {
        ull a = 0;
        const ulonglong2* WQ = (const ulonglong2*)g_menc_W2Q;
#pragma unroll 4
        for (int kq = 0; kq < 32; kq++) {
            ulonglong2 w = WQ[kq * EMBED + t];
            ulonglong2 z = *(const ulonglong2*)&Spre[4 * kq];
            a = f2fma(z.x, w.x, a);
            a = f2fma(z.y, w.y, a);
        }
        mergeds[t] = f2sum(a) + menc_b2[t];
    }
    __syncthreads();

    // ================= final decode: main pass cols {t, t+128} ===============
    float* dout = &cand[0][0];   // cand dead now; reuse as dout[288]
    {
        const ulonglong2* WQ = (const ulonglong2*)g_dec_WxQ;
        ull a0 = 0, a1 = 0;
#pragma unroll 4
        for (int kq = 0; kq < 32; kq++) {
            ulonglong2 w0 = WQ[kq * OUTC + t];
            ulonglong2 w1 = WQ[kq * OUTC + t + 128];
            ulonglong2 z = *(const ulonglong2*)&mergeds[4 * kq];
            a0 = f2fma(z.x, w0.x, a0);
            a0 = f2fma(z.y, w0.y, a0);
            a1 = f2fma(z.x, w1.x, a1);
            a1 = f2fma(z.y, w1.y, a1);
        }
        dout[t]       = f2sum(a0) + dec_bx[t];
        dout[t + 128] = f2sum(a1) + dec_bx[t + 128];
    }
    // tail: cols 256..287 split-K on warps 0/1; dec logits split-K on warps 2/3
    {
        const int kq0 = (wrp & 1) ? 16 : 0;
        if (wrp < 2) {
            const int c = 256 + lane;
            const ulonglong2* WQ = (const ulonglong2*)g_dec_WxQ;
            ull a = 0;
#pragma unroll 4
            for (int kq = kq0; kq < kq0 + 16; kq++) {
                ulonglong2 w = WQ[kq * OUTC + c];
                ulonglong2 z = *(const ulonglong2*)&mergeds[4 * kq];
                a = f2fma(z.x, w.x, a);
                a = f2fma(z.y, w.y, a);
            }
            if (wrp == 0) psA[lane] = f2sum(a);
            else          psB[lane] = f2sum(a);
        } else if (lane < NLOG) {
            const int s = lane;
            const ulonglong2* WsQ = (const ulonglong2*)g_dec_WsQ;
            ull a = 0;
#pragma unroll 4
            for (int kq = kq0; kq < kq0 + 16; kq++) {
                ulonglong2 w = WsQ[kq * NLOG + s];
                ulonglong2 z = *(const ulonglong2*)&mergeds[4 * kq];
                a = f2fma(z.x, w.x, a);
                a = f2fma(z.y, w.y, a);
            }
            if (wrp == 2) dlogA[s] = f2sum(a) + dec_bs[s];
            else          dlogB[s] = f2sum(a);
        }
    }
    __syncthreads();
    if (t == 0) {
        float best = dlogA[0] + dlogB[0]; int bi = 0;
#pragma unroll
        for (int c = 1; c < NLOG; c++) {
            const float v = dlogA[c] + dlogB[c];
            if (v > best) { best = v; bi = c; }
        }
        n2s = bi;
    }
    if (t < 32) dout[256 + t] = psA[t] + psB[t] + dec_bx[256 + t];
    __syncthreads();
    const int n2 = n2s;

    // masked writes
    {
        int c = t;
        out[(size_t)i * OUTC + c] = ((c / ORIG) < n2) ? dout[c] : 0.f;
        c = t + 128;
        out[(size_t)i * OUTC + c] = ((c / ORIG) < n2) ? dout[c] : 0.f;
        if (t < 32) {
            c = t + 256;
            out[(size_t)i * OUTC + c] = ((c / ORIG) < n2) ? dout[c] : 0.f;
        }
    }
    if (write_extra && t < MAX_OBJ) {
        const size_t batch_off = (size_t)A_N * OUTC;
        const size_t mask_off  = batch_off + (size_t)A_N * MAX_OBJ;
        out[batch_off + (size_t)i * MAX_OBJ + t] = (float)i;
        out[mask_off  + (size_t)i * MAX_OBJ + t] = (t < n2) ? 1.f : 0.f;
    }
}

extern "C" void kernel_launch(void* const* d_in, const int* in_sizes, int n_in,
                              void* d_out, int out_size) {
    const float* obj_x     = (const float*)d_in[0];
    const float* obj_pos   = (const float*)d_in[1];
    const float* agent_pos = (const float*)d_in[2];
    const float* enc_W1    = (const float*)d_in[3];
    const float* enc_b1    = (const float*)d_in[4];
    const float* enc_W2    = (const float*)d_in[5];
    const float* enc_b2    = (const float*)d_in[6];
    const float* mdec_Ws   = (const float*)d_in[7];
    const float* mdec_bs   = (const float*)d_in[8];
    const float* mdec_Wx   = (const float*)d_in[9];
    const float* mdec_bx   = (const float*)d_in[10];
    const float* menc_W1   = (const float*)d_in[11];
    const float* menc_b1   = (const float*)d_in[12];
    const float* menc_W2   = (const float*)d_in[13];
    const float* menc_b2   = (const float*)d_in[14];
    const float* dec_Ws    = (const float*)d_in[15];
    const float* dec_bs    = (const float*)d_in[16];
    const float* dec_Wx    = (const float*)d_in[17];
    const float* dec_bx    = (const float*)d_in[18];
    const int*   obs_ei    = (const int*)d_in[19];   // row0 = tgt, row1 = src
    const int*   comm_ei   = (const int*)d_in[20];   // row0 = src(j), row1 = tgt(i)

    const int* obs_src  = obs_ei  + A_N * OBS_DEG;   // row 1
    const int* comm_src = comm_ei;                   // row 0

    pre_kernel<<<A_N + PREP_BLOCKS, 128>>>(obj_x, obj_pos, agent_pos,
                                           enc_W1, enc_b1, enc_W2, enc_b2, obs_src,
                                           mdec_Wx, dec_Wx, menc_W2, mdec_Ws, dec_Ws);

    mdec_kernel<<<A_N / 8, 128>>>(mdec_bs, mdec_bx);

    const int full = A_N * OUTC + 2 * A_N * MAX_OBJ;   // decoded + batch + mask
    const int write_extra = (out_size >= full) ? 1 : 0;

    agent_kernel<<<A_N, 128>>>(agent_pos,
                               menc_W1, menc_b1, menc_b2,
                               dec_bs, dec_bx,
                               comm_src, (float*)d_out, write_extra);
}

// round 6
// speedup vs baseline: 2.1396x; 1.0810x over previous
#include <cuda_runtime.h>
#include <cuda_bf16.h>

#define A_N      4096
#define N_OBJ    8192
#define IN_DIM   16
#define EMBED    128
#define MAX_OBJ  16
#define DEG      8
#define OBS_DEG  8
#define POS_DIM  2
#define ORIG     18          // IN_DIM + POS_DIM
#define ORIG_P   20          // padded row stride (80B, 16B aligned)
#define OUTC     288         // MAX_OBJ * ORIG
#define NLOG     17          // MAX_OBJ + 1
#define KTOT     128         // DEG * MAX_OBJ
#define THRES    0.02f

typedef unsigned long long ull;

__device__ __forceinline__ ull f2fma(ull a, ull b, ull c) {
    ull d;
    asm("fma.rn.f32x2 %0, %1, %2, %3;" : "=l"(d) : "l"(a), "l"(b), "l"(c));
    return d;
}
__device__ __forceinline__ float f2sum(ull v) {
    float lo, hi;
    asm("mov.b64 {%0, %1}, %2;" : "=f"(lo), "=f"(hi) : "l"(v));
    return lo + hi;
}
__device__ __forceinline__ ull f2pack(float lo, float hi) {
    ull v;
    asm("mov.b64 %0, {%1, %2};" : "=l"(v) : "f"(lo), "f"(hi));
    return v;
}

// ---------------- device scratch ----------------
__device__ float  g_enc[A_N * EMBED];
__device__ float  g_elems0[A_N * OUTC];    // per-source decoded elems (pre relpos)
__device__ int    g_npred[A_N];            // per-source argmax count
// k-quad interleaved: Q[kq*cols + c] = {W[4kq][c], W[4kq+1][c], W[4kq+2][c], W[4kq+3][c]}
__device__ float4 g_mdec_WxQ[32 * OUTC];
__device__ float4 g_dec_WxQ [32 * OUTC];
__device__ float4 g_menc_W2Q[32 * EMBED];
__device__ float4 g_enc_W2Q [32 * EMBED];
__device__ float4 g_mdec_WsQ[32 * NLOG];
__device__ float4 g_dec_WsQ [32 * NLOG];

#define PREP_TOTAL (32 * OUTC + 32 * OUTC + 32 * EMBED + 32 * EMBED + 32 * NLOG + 32 * NLOG)
#define PREP_BLOCKS ((PREP_TOTAL + 127) / 128)
#define ENC_BLOCKS (A_N / 8)

__device__ __forceinline__ float4 quad(const float* __restrict__ W, int cols, int kq, int c) {
    return make_float4(W[(4 * kq    ) * cols + c], W[(4 * kq + 1) * cols + c],
                       W[(4 * kq + 2) * cols + c], W[(4 * kq + 3) * cols + c]);
}

// ---------------------------------------------------------------------------
// Kernel A (fused): blocks [0,512) = obs encode (8 agents each);
//                   blocks >= 512 = weight prep.
// ---------------------------------------------------------------------------
__global__ __launch_bounds__(128) void pre_kernel(
    const float* __restrict__ obj_x, const float* __restrict__ obj_pos,
    const float* __restrict__ agent_pos,
    const float* __restrict__ W1, const float* __restrict__ b1,
    const float* __restrict__ b2,
    const int*   __restrict__ obs_src,
    const float* __restrict__ mWx, const float* __restrict__ dWx,
    const float* __restrict__ mW2, const float* __restrict__ eW2,
    const float* __restrict__ mWs, const float* __restrict__ dWs)
{
    const int t = threadIdx.x;

    if (blockIdx.x >= ENC_BLOCKS) {
        int idx = (blockIdx.x - ENC_BLOCKS) * 128 + t;
        if (idx < 32 * OUTC) { g_mdec_WxQ[idx] = quad(mWx, OUTC, idx / OUTC, idx % OUTC); return; }
        idx -= 32 * OUTC;
        if (idx < 32 * OUTC) { g_dec_WxQ[idx]  = quad(dWx, OUTC, idx / OUTC, idx % OUTC); return; }
        idx -= 32 * OUTC;
        if (idx < 32 * EMBED) { g_menc_W2Q[idx] = quad(mW2, EMBED, idx / EMBED, idx % EMBED); return; }
        idx -= 32 * EMBED;
        if (idx < 32 * EMBED) { g_enc_W2Q[idx]  = quad(eW2, EMBED, idx / EMBED, idx % EMBED); return; }
        idx -= 32 * EMBED;
        if (idx < 32 * NLOG) { g_mdec_WsQ[idx] = quad(mWs, NLOG, idx / NLOG, idx % NLOG); return; }
        idx -= 32 * NLOG;
        if (idx < 32 * NLOG) { g_dec_WsQ[idx]  = quad(dWs, NLOG, idx / NLOG, idx % NLOG); return; }
        return;
    }

    const int a0 = blockIdx.x * 8;

    __shared__ __align__(16) float msg[8 * OBS_DEG][ORIG_P];   // 64 rows
    __shared__ __align__(16) float S[8][EMBED];
    __shared__ float apos[8][2];

    if (t < 16) apos[t >> 1][t & 1] = agent_pos[(a0 + (t >> 1)) * 2 + (t & 1)];
    __syncthreads();

    // build 64 messages (64*18 = 1152 entries)
    for (int idx = t; idx < 8 * OBS_DEG * ORIG; idx += 128) {
        const int r = idx / ORIG;           // 0..63
        const int k = idx - r * ORIG;
        const int ag = r >> 3;
        const int e  = r & 7;
        const int o = obs_src[(a0 + ag) * OBS_DEG + e];
        float v;
        if (k < IN_DIM) v = obj_x[o * IN_DIM + k];
        else            v = obj_pos[o * POS_DIM + (k - IN_DIM)] - apos[ag][k - IN_DIM];
        msg[r][k] = v;
    }
    __syncthreads();

    // W1 column t loaded once, reused across 64 rows
    ull w1p[9];
#pragma unroll
    for (int q = 0; q < 9; q++)
        w1p[q] = f2pack(W1[(2 * q) * EMBED + t], W1[(2 * q + 1) * EMBED + t]);
    const float b1t = b1[t];

#pragma unroll 1
    for (int ag = 0; ag < 8; ag++) {
        float acc = 0.f;
#pragma unroll
        for (int e = 0; e < OBS_DEG; e++) {
            const ulonglong2* r = (const ulonglong2*)msg[ag * OBS_DEG + e];
            ulonglong2 q0 = r[0], q1 = r[1], q2 = r[2], q3 = r[3];
            ull q4 = ((const ull*)msg[ag * OBS_DEG + e])[8];
            ull h = 0;
            h = f2fma(q0.x, w1p[0], h); h = f2fma(q0.y, w1p[1], h);
            h = f2fma(q1.x, w1p[2], h); h = f2fma(q1.y, w1p[3], h);
            h = f2fma(q2.x, w1p[4], h); h = f2fma(q2.y, w1p[5], h);
            h = f2fma(q3.x, w1p[6], h); h = f2fma(q3.y, w1p[7], h);
            h = f2fma(q4,   w1p[8], h);
            acc += fmaxf(f2sum(h) + b1t, 0.f);
        }
        S[ag][t] = acc;
    }
    __syncthreads();

    // W2 GEMV: 8 accumulators share each weight load
    {
        const ulonglong2* WQ = (const ulonglong2*)g_enc_W2Q;
        ull ao[8];
#pragma unroll
        for (int ag = 0; ag < 8; ag++) ao[ag] = 0;
#pragma unroll 2
        for (int kq = 0; kq < 32; kq++) {
            ulonglong2 w = WQ[kq * EMBED + t];
#pragma unroll
            for (int ag = 0; ag < 8; ag++) {
                ulonglong2 z = *(const ulonglong2*)&S[ag][4 * kq];
                ao[ag] = f2fma(z.x, w.x, ao[ag]);
                ao[ag] = f2fma(z.y, w.y, ao[ag]);
            }
        }
        const float b2t = b2[t];
#pragma unroll
        for (int ag = 0; ag < 8; ag++)
            g_enc[(a0 + ag) * EMBED + t] = f2sum(ao[ag]) + b2t;
    }
}

// ---------------------------------------------------------------------------
// Kernel A2: per-SOURCE mdec decode, batch 8 agents per block.
// ---------------------------------------------------------------------------
__global__ __launch_bounds__(128) void mdec_kernel(
    const float* __restrict__ mdec_bs, const float* __restrict__ mdec_bx)
{
    const int j0 = blockIdx.x * 8;
    const int t = threadIdx.x;
    const int lane = t & 31;
    const int wrp  = t >> 5;

    __shared__ __align__(16) float zj[DEG][EMBED];
    __shared__ float psA[32][DEG], psB[32][DEG];
    __shared__ float logitsA[DEG][NLOG], logitsB[DEG][NLOG];

#pragma unroll
    for (int e = 0; e < DEG; e++) zj[e][t] = g_enc[(j0 + e) * EMBED + t];
    __syncthreads();

    {
        const ulonglong2* WQ = (const ulonglong2*)g_mdec_WxQ;
        ull acc0[DEG], acc1[DEG];
#pragma unroll
        for (int e = 0; e < DEG; e++) { acc0[e] = 0; acc1[e] = 0; }
#pragma unroll 2
        for (int kq = 0; kq < 32; kq++) {
            ulonglong2 w0 = WQ[kq * OUTC + t];
            ulonglong2 w1 = WQ[kq * OUTC + t + 128];
#pragma unroll
            for (int e = 0; e < DEG; e++) {
                ulonglong2 z = *(const ulonglong2*)&zj[e][4 * kq];
                acc0[e] = f2fma(z.x, w0.x, acc0[e]);
                acc0[e] = f2fma(z.y, w0.y, acc0[e]);
                acc1[e] = f2fma(z.x, w1.x, acc1[e]);
                acc1[e] = f2fma(z.y, w1.y, acc1[e]);
            }
        }
        const float bx0 = mdec_bx[t];
        const float bx1 = mdec_bx[t + 128];
#pragma unroll
        for (int e = 0; e < DEG; e++) {
            g_elems0[(j0 + e) * OUTC + t]       = f2sum(acc0[e]) + bx0;
            g_elems0[(j0 + e) * OUTC + t + 128] = f2sum(acc1[e]) + bx1;
        }
    }
    {
        const int kq0 = (wrp & 1) ? 16 : 0;
        if (wrp < 2) {
            const int c = 256 + lane;
            const ulonglong2* WQ = (const ulonglong2*)g_mdec_WxQ;
            ull acc[DEG];
#pragma unroll
            for (int e = 0; e < DEG; e++) acc[e] = 0;
#pragma unroll 4
            for (int kq = kq0; kq < kq0 + 16; kq++) {
                ulonglong2 w = WQ[kq * OUTC + c];
#pragma unroll
                for (int e = 0; e < DEG; e++) {
                    ulonglong2 z = *(const ulonglong2*)&zj[e][4 * kq];
                    acc[e] = f2fma(z.x, w.x, acc[e]);
                    acc[e] = f2fma(z.y, w.y, acc[e]);
                }
            }
            if (wrp == 0) {
#pragma unroll
                for (int e = 0; e < DEG; e++) psA[lane][e] = f2sum(acc[e]);
            } else {
#pragma unroll
                for (int e = 0; e < DEG; e++) psB[lane][e] = f2sum(acc[e]);
            }
        } else if (lane < NLOG) {
            const int s = lane;
            const ulonglong2* WsQ = (const ulonglong2*)g_mdec_WsQ;
            ull acc[DEG];
#pragma unroll
            for (int e = 0; e < DEG; e++) acc[e] = 0;
#pragma unroll 4
            for (int kq = kq0; kq < kq0 + 16; kq++) {
                ulonglong2 w = WsQ[kq * NLOG + s];
#pragma unroll
                for (int e = 0; e < DEG; e++) {
                    ulonglong2 z = *(const ulonglong2*)&zj[e][4 * kq];
                    acc[e] = f2fma(z.x, w.x, acc[e]);
                    acc[e] = f2fma(z.y, w.y, acc[e]);
                }
            }
            if (wrp == 2) {
                const float bs = mdec_bs[s];
#pragma unroll
                for (int e = 0; e < DEG; e++) logitsA[e][s] = f2sum(acc[e]) + bs;
            } else {
#pragma unroll
                for (int e = 0; e < DEG; e++) logitsB[e][s] = f2sum(acc[e]);
            }
        }
    }
    __syncthreads();

#pragma unroll
    for (int r = 0; r < 2; r++) {
        const int p = t + r * 128;
        const int cl = p >> 3;
        const int e  = p & 7;
        const int c  = 256 + cl;
        g_elems0[(j0 + e) * OUTC + c] = psA[cl][e] + psB[cl][e] + mdec_bx[c];
    }
    if (t < DEG) {
        float best = logitsA[t][0] + logitsB[t][0]; int bi = 0;
#pragma unroll
        for (int c = 1; c < NLOG; c++) {
            const float v = logitsA[t][c] + logitsB[t][c];
            if (v > best) { best = v; bi = c; }
        }
        g_npred[j0 + t] = bi;
    }
}

// ---------------------------------------------------------------------------
// Kernel B: 2 agents per block. Gather/dedup serialized per agent; the
// weight-heavy phases (merge-encode, W2, dec) share weight loads across both.
// ---------------------------------------------------------------------------
__global__ __launch_bounds__(128) void agent_kernel(
    const float* __restrict__ agent_pos,
    const float* __restrict__ menc_W1, const float* __restrict__ menc_b1,
    const float* __restrict__ menc_b2,
    const float* __restrict__ dec_bs,  const float* __restrict__ dec_bx,
    const int*   __restrict__ comm_src,
    float* __restrict__ out, int write_extra)
{
    const int i0 = blockIdx.x * 2;
    const int t = threadIdx.x;
    const int lane = t & 31;
    const int wrp  = t >> 5;

    __shared__ __align__(16) float cand[2][KTOT][ORIG_P];   // 20 KB
    __shared__ __align__(16) float Spre[2][EMBED];
    __shared__ __align__(16) float mergeds[2][EMBED];
    __shared__ float psA[2][32], psB[2][32];
    __shared__ int   npred2[2][DEG];
    __shared__ int   keepf[KTOT];
    __shared__ float cpx[KTOT], cpy[KTOT];
    __shared__ int   cidx[KTOT];
    __shared__ float relx[2][DEG], rely[2][DEG];
    __shared__ int   jidx[2][DEG];
    __shared__ float dlogA[2][NLOG], dlogB[2][NLOG];
    __shared__ int   kidx2[2][MAX_OBJ];
    __shared__ int   ncnt2[2];
    __shared__ int   wtot[4], wtot2[4];
    __shared__ int   n2s[2];

    if (t < 16) {
        const int ag = t >> 3, e = t & 7;
        const int i = i0 + ag;
        const int j = comm_src[i * DEG + e];
        jidx[ag][e] = j;
        relx[ag][e] = agent_pos[2 * j    ] - agent_pos[2 * i    ];
        rely[ag][e] = agent_pos[2 * j + 1] - agent_pos[2 * i + 1];
        npred2[ag][e] = g_npred[j];
    }
    __syncthreads();

    // ---- gather cand for both agents ----
#pragma unroll 1
    for (int ag = 0; ag < 2; ag++) {
#pragma unroll
        for (int e = 0; e < DEG; e++) {
            const float* src = &g_elems0[jidx[ag][e] * OUTC];
            const float rx = relx[ag][e], ry = rely[ag][e];
            {
                const int c = t, m = c / ORIG, dim = c - m * ORIG;
                float v = src[c];
                if (dim == 16) v += rx;
                if (dim == 17) v += ry;
                cand[ag][e * MAX_OBJ + m][dim] = v;
            }
            {
                const int c = t + 128, m = c / ORIG, dim = c - m * ORIG;
                float v = src[c];
                if (dim == 16) v += rx;
                if (dim == 17) v += ry;
                cand[ag][e * MAX_OBJ + m][dim] = v;
            }
            if (t < 32) {
                const int c = t + 256, m = c / ORIG, dim = c - m * ORIG;
                float v = src[c];
                if (dim == 16) v += rx;
                if (dim == 17) v += ry;
                cand[ag][e * MAX_OBJ + m][dim] = v;
            }
        }
    }
    __syncthreads();

    // ---- validity + compact + dedup + cap, per agent (serialized) ----
#pragma unroll 1
    for (int ag = 0; ag < 2; ag++) {
        const int em = t >> 4, mm = t & 15;
        const int v0 = (mm < npred2[ag][em]) ? 1 : 0;
        const float x0 = cand[ag][t][16], y0 = cand[ag][t][17];

        unsigned bm = __ballot_sync(0xffffffffu, v0);
        int pre = __popc(bm & ((1u << lane) - 1u));
        if (lane == 31) wtot[wrp] = pre + v0;
        keepf[t] = 0;
        __syncthreads();
        int off = 0;
#pragma unroll
        for (int q = 0; q < 4; q++) if (q < wrp) off += wtot[q];
        const int nv = wtot[0] + wtot[1] + wtot[2] + wtot[3];
        if (v0) { const int p = off + pre; cpx[p] = x0; cpy[p] = y0; cidx[p] = t; }
        __syncthreads();

        if (t < nv) {
            const float xx = cpx[t], yy = cpy[t];
            int dead = 0;
            for (int k = 0; k < t; k++) {
                const float dx = xx - cpx[k];
                const float dy = yy - cpy[k];
                if (sqrtf(fmaf(dx, dx, dy * dy)) < THRES) dead = 1;
            }
            if (!dead) keepf[cidx[t]] = 1;
        }
        __syncthreads();

        const int k2 = keepf[t];
        unsigned bm2 = __ballot_sync(0xffffffffu, k2);
        int pre2 = __popc(bm2 & ((1u << lane) - 1u));
        if (lane == 31) wtot2[wrp] = pre2 + k2;
        __syncthreads();
        int off2 = 0;
#pragma unroll
        for (int q = 0; q < 4; q++) if (q < wrp) off2 += wtot2[q];
        const int tot2 = wtot2[0] + wtot2[1] + wtot2[2] + wtot2[3];
        const int excl = off2 + pre2;
        if (k2 && (excl + 1 <= MAX_OBJ - 1)) kidx2[ag][excl] = t;
        if (t == 0) ncnt2[ag] = (tot2 < MAX_OBJ - 1) ? tot2 : (MAX_OBJ - 1);
        __syncthreads();
    }

    // ---- merge encode: shared W1 registers feed both agents ----
    {
        ull w1p[9];
#pragma unroll
        for (int q = 0; q < 9; q++)
            w1p[q] = f2pack(menc_W1[(2 * q) * EMBED + t], menc_W1[(2 * q + 1) * EMBED + t]);
        const float b1t = menc_b1[t];
#pragma unroll 1
        for (int ag = 0; ag < 2; ag++) {
            const int ncnt = ncnt2[ag];
            float acc = 0.f;
            for (int l = 0; l < ncnt; l++) {
                const int li = kidx2[ag][l];
                const ulonglong2* r = (const ulonglong2*)cand[ag][li];
                ulonglong2 q0 = r[0], q1 = r[1], q2 = r[2], q3 = r[3];
                ull q4 = ((const ull*)cand[ag][li])[8];
                ull h = 0;
                h = f2fma(q0.x, w1p[0], h); h = f2fma(q0.y, w1p[1], h);
                h = f2fma(q1.x, w1p[2], h); h = f2fma(q1.y, w1p[3], h);
                h = f2fma(q2.x, w1p[4], h); h = f2fma(q2.y, w1p[5], h);
                h = f2fma(q3.x, w1p[6], h); h = f2fma(q3.y, w1p[7], h);
                h = f2fma(q4,   w1p[8], h);
                acc += fmaxf(f2sum(h) + b1t, 0.f);
            }
            Spre[ag][t] = acc;
        }
    }
    __syncthreads();

    // merged = Spre @ menc_W2 + b2 : both agents share each weight load
    {
        ull a0 = 0, a1 = 0;
        const ulonglong2* WQ = (const ulonglong2*)g_menc_W2Q;
#pragma unroll 4
        for (int kq = 0; kq < 32; kq++) {
            ulonglong2 w = WQ[kq * EMBED + t];
            ulonglong2 z0 = *(const ulonglong2*)&Spre[0][4 * kq];
            ulonglong2 z1 = *(const ulonglong2*)&Spre[1][4 * kq];
            a0 = f2fma(z0.x, w.x, a0);
            a0 = f2fma(z0.y, w.y, a0);
            a1 = f2fma(z1.x, w.x, a1);
            a1 = f2fma(z1.y, w.y, a1);
        }
        const float b2t = menc_b2[t];
        mergeds[0][t] = f2sum(a0) + b2t;
        mergeds[1][t] = f2sum(a1) + b2t;
    }
    __syncthreads();

    // ---- final decode: cols {t, t+128} x 2 agents share weight loads ----
    float* dout = &cand[0][0][0];   // cand dead now; reuse as dout[2][288]
    {
        const ulonglong2* WQ = (const ulonglong2*)g_dec_WxQ;
        ull a00 = 0, a01 = 0, a10 = 0, a11 = 0;
#pragma unroll 2
        for (int kq = 0; kq < 32; kq++) {
            ulonglong2 w0 = WQ[kq * OUTC + t];
            ulonglong2 w1 = WQ[kq * OUTC + t + 128];
            ulonglong2 z0 = *(const ulonglong2*)&mergeds[0][4 * kq];
            ulonglong2 z1 = *(const ulonglong2*)&mergeds[1][4 * kq];
            a00 = f2fma(z0.x, w0.x, a00); a00 = f2fma(z0.y, w0.y, a00);
            a01 = f2fma(z0.x, w1.x, a01); a01 = f2fma(z0.y, w1.y, a01);
            a10 = f2fma(z1.x, w0.x, a10); a10 = f2fma(z1.y, w0.y, a10);
            a11 = f2fma(z1.x, w1.x, a11); a11 = f2fma(z1.y, w1.y, a11);
        }
        const float bxa = dec_bx[t], bxb = dec_bx[t + 128];
        dout[t]             = f2sum(a00) + bxa;
        dout[t + 128]       = f2sum(a01) + bxb;
        dout[288 + t]       = f2sum(a10) + bxa;
        dout[288 + t + 128] = f2sum(a11) + bxb;
    }
    // tail cols 256..287 split-K warps 0/1 (both agents); logits warps 2/3
    {
        const int kq0 = (wrp & 1) ? 16 : 0;
        if (wrp < 2) {
            const int c = 256 + lane;
            const ulonglong2* WQ = (const ulonglong2*)g_dec_WxQ;
            ull a0 = 0, a1 = 0;
#pragma unroll 4
            for (int kq = kq0; kq < kq0 + 16; kq++) {
                ulonglong2 w = WQ[kq * OUTC + c];
                ulonglong2 z0 = *(const ulonglong2*)&mergeds[0][4 * kq];
                ulonglong2 z1 = *(const ulonglong2*)&mergeds[1][4 * kq];
                a0 = f2fma(z0.x, w.x, a0); a0 = f2fma(z0.y, w.y, a0);
                a1 = f2fma(z1.x, w.x, a1); a1 = f2fma(z1.y, w.y, a1);
            }
            if (wrp == 0) { psA[0][lane] = f2sum(a0); psA[1][lane] = f2sum(a1); }
            else          { psB[0][lane] = f2sum(a0); psB[1][lane] = f2sum(a1); }
        } else if (lane < NLOG) {
            const int s = lane;
            const ulonglong2* WsQ = (const ulonglong2*)g_dec_WsQ;
            ull a0 = 0, a1 = 0;
#pragma unroll 4
            for (int kq = kq0; kq < kq0 + 16; kq++) {
                ulonglong2 w = WsQ[kq * NLOG + s];
                ulonglong2 z0 = *(const ulonglong2*)&mergeds[0][4 * kq];
                ulonglong2 z1 = *(const ulonglong2*)&mergeds[1][4 * kq];
                a0 = f2fma(z0.x, w.x, a0); a0 = f2fma(z0.y, w.y, a0);
                a1 = f2fma(z1.x, w.x, a1); a1 = f2fma(z1.y, w.y, a1);
            }
            if (wrp == 2) {
                const float bs = dec_bs[s];
                dlogA[0][s] = f2sum(a0) + bs;
                dlogA[1][s] = f2sum(a1) + bs;
            } else {
                dlogB[0][s] = f2sum(a0);
                dlogB[1][s] = f2sum(a1);
            }
        }
    }
    __syncthreads();
    if (t < 2) {
        float best = dlogA[t][0] + dlogB[t][0]; int bi = 0;
#pragma unroll
        for (int c = 1; c < NLOG; c++) {
            const float v = dlogA[t][c] + dlogB[t][c];
            if (v > best) { best = v; bi = c; }
        }
        n2s[t] = bi;
    }
    if (t < 32) {
        const float bx = dec_bx[256 + t];
        dout[256 + t]       = psA[0][t] + psB[0][t] + bx;
        dout[288 + 256 + t] = psA[1][t] + psB[1][t] + bx;
    }
    __syncthreads();

    // masked writes for both agents
#pragma unroll 1
    for (int ag = 0; ag < 2; ag++) {
        const int i = i0 + ag;
        const int n2 = n2s[ag];
        const float* d = dout + ag * 288;
        int c = t;
        out[(size_t)i * OUTC + c] = ((c / ORIG) < n2) ? d[c] : 0.f;
        c = t + 128;
        out[(size_t)i * OUTC + c] = ((c / ORIG) < n2) ? d[c] : 0.f;
        if (t < 32) {
            c = t + 256;
            out[(size_t)i * OUTC + c] = ((c / ORIG) < n2) ? d[c] : 0.f;
        }
        if (write_extra && t < MAX_OBJ) {
            const size_t batch_off = (size_t)A_N * OUTC;
            const size_t mask_off  = batch_off + (size_t)A_N * MAX_OBJ;
            out[batch_off + (size_t)i * MAX_OBJ + t] = (float)i;
            out[mask_off  + (size_t)i * MAX_OBJ + t] = (t < n2) ? 1.f : 0.f;
        }
    }
}

extern "C" void kernel_launch(void* const* d_in, const int* in_sizes, int n_in,
                              void* d_out, int out_size) {
    const float* obj_x     = (const float*)d_in[0];
    const float* obj_pos   = (const float*)d_in[1];
    const float* agent_pos = (const float*)d_in[2];
    const float* enc_W1    = (const float*)d_in[3];
    const float* enc_b1    = (const float*)d_in[4];
    const float* enc_W2    = (const float*)d_in[5];
    const float* enc_b2    = (const float*)d_in[6];
    const float* mdec_Ws   = (const float*)d_in[7];
    const float* mdec_bs   = (const float*)d_in[8];
    const float* mdec_Wx   = (const float*)d_in[9];
    const float* mdec_bx   = (const float*)d_in[10];
    const float* menc_W1   = (const float*)d_in[11];
    const float* menc_b1   = (const float*)d_in[12];
    const float* menc_W2   = (const float*)d_in[13];
    const float* menc_b2   = (const float*)d_in[14];
    const float* dec_Ws    = (const float*)d_in[15];
    const float* dec_bs    = (const float*)d_in[16];
    const float* dec_Wx    = (const float*)d_in[17];
    const float* dec_bx    = (const float*)d_in[18];
    const int*   obs_ei    = (const int*)d_in[19];   // row0 = tgt, row1 = src
    const int*   comm_ei   = (const int*)d_in[20];   // row0 = src(j), row1 = tgt(i)

    const int* obs_src  = obs_ei  + A_N * OBS_DEG;   // row 1
    const int* comm_src = comm_ei;                   // row 0

    pre_kernel<<<ENC_BLOCKS + PREP_BLOCKS, 128>>>(obj_x, obj_pos, agent_pos,
                                                  enc_W1, enc_b1, enc_b2, obs_src,
                                                  mdec_Wx, dec_Wx, menc_W2, enc_W2,
                                                  mdec_Ws, dec_Ws);

    mdec_kernel<<<A_N / 8, 128>>>(mdec_bs, mdec_bx);

    const int full = A_N * OUTC + 2 * A_N * MAX_OBJ;   // decoded + batch + mask
    const int write_extra = (out_size >= full) ? 1 : 0;

    agent_kernel<<<A_N / 2, 128>>>(agent_pos,
                                   menc_W1, menc_b1, menc_b2,
                                   dec_bs, dec_bx,
                                   comm_src, (float*)d_out, write_extra);
}

// round 7
// speedup vs baseline: 2.4447x; 1.1426x over previous
#include <cuda_runtime.h>
#include <cuda_bf16.h>

#define A_N      4096
#define N_OBJ    8192
#define IN_DIM   16
#define EMBED    128
#define MAX_OBJ  16
#define DEG      8
#define OBS_DEG  8
#define POS_DIM  2
#define ORIG     18          // IN_DIM + POS_DIM
#define ORIG_P   20          // padded row stride (80B, 16B aligned)
#define OUTC     288         // MAX_OBJ * ORIG
#define NLOG     17          // MAX_OBJ + 1
#define KTOT     128         // DEG * MAX_OBJ
#define THRES    0.02f

typedef unsigned long long ull;

__device__ __forceinline__ ull f2fma(ull a, ull b, ull c) {
    ull d;
    asm("fma.rn.f32x2 %0, %1, %2, %3;" : "=l"(d) : "l"(a), "l"(b), "l"(c));
    return d;
}
__device__ __forceinline__ float f2sum(ull v) {
    float lo, hi;
    asm("mov.b64 {%0, %1}, %2;" : "=f"(lo), "=f"(hi) : "l"(v));
    return lo + hi;
}
__device__ __forceinline__ ull f2pack(float lo, float hi) {
    ull v;
    asm("mov.b64 %0, {%1, %2};" : "=l"(v) : "f"(lo), "f"(hi));
    return v;
}

// ---------------- device scratch ----------------
__device__ float  g_enc[A_N * EMBED];
__device__ float  g_elems0[A_N * OUTC];    // per-source decoded elems (pre relpos)
__device__ int    g_npred[A_N];            // per-source argmax count
__device__ float  g_Spre[A_N * EMBED];     // per-agent merge-encode sum
// k-quad interleaved: Q[kq*cols + c] = {W[4kq][c], W[4kq+1][c], W[4kq+2][c], W[4kq+3][c]}
__device__ float4 g_mdec_WxQ[32 * OUTC];
__device__ float4 g_dec_WxQ [32 * OUTC];
__device__ float4 g_menc_W2Q[32 * EMBED];
__device__ float4 g_enc_W2Q [32 * EMBED];
__device__ float4 g_mdec_WsQ[32 * NLOG];
__device__ float4 g_dec_WsQ [32 * NLOG];

#define PREP_TOTAL (32 * OUTC + 32 * OUTC + 32 * EMBED + 32 * EMBED + 32 * NLOG + 32 * NLOG)
#define PREP_BLOCKS ((PREP_TOTAL + 127) / 128)
#define ENC_BLOCKS (A_N / 4)

__device__ __forceinline__ float4 quad(const float* __restrict__ W, int cols, int kq, int c) {
    return make_float4(W[(4 * kq    ) * cols + c], W[(4 * kq + 1) * cols + c],
                       W[(4 * kq + 2) * cols + c], W[(4 * kq + 3) * cols + c]);
}

// ---------------------------------------------------------------------------
// K1: blocks [0,1024) = obs encode (4 agents each); rest = weight prep.
// ---------------------------------------------------------------------------
__global__ __launch_bounds__(128) void pre_kernel(
    const float* __restrict__ obj_x, const float* __restrict__ obj_pos,
    const float* __restrict__ agent_pos,
    const float* __restrict__ W1, const float* __restrict__ b1,
    const float* __restrict__ b2,
    const int*   __restrict__ obs_src,
    const float* __restrict__ mWx, const float* __restrict__ dWx,
    const float* __restrict__ mW2, const float* __restrict__ eW2,
    const float* __restrict__ mWs, const float* __restrict__ dWs)
{
    const int t = threadIdx.x;

    if (blockIdx.x >= ENC_BLOCKS) {
        int idx = (blockIdx.x - ENC_BLOCKS) * 128 + t;
        if (idx < 32 * OUTC) { g_mdec_WxQ[idx] = quad(mWx, OUTC, idx / OUTC, idx % OUTC); return; }
        idx -= 32 * OUTC;
        if (idx < 32 * OUTC) { g_dec_WxQ[idx]  = quad(dWx, OUTC, idx / OUTC, idx % OUTC); return; }
        idx -= 32 * OUTC;
        if (idx < 32 * EMBED) { g_menc_W2Q[idx] = quad(mW2, EMBED, idx / EMBED, idx % EMBED); return; }
        idx -= 32 * EMBED;
        if (idx < 32 * EMBED) { g_enc_W2Q[idx]  = quad(eW2, EMBED, idx / EMBED, idx % EMBED); return; }
        idx -= 32 * EMBED;
        if (idx < 32 * NLOG) { g_mdec_WsQ[idx] = quad(mWs, NLOG, idx / NLOG, idx % NLOG); return; }
        idx -= 32 * NLOG;
        if (idx < 32 * NLOG) { g_dec_WsQ[idx]  = quad(dWs, NLOG, idx / NLOG, idx % NLOG); return; }
        return;
    }

    const int a0 = blockIdx.x * 4;

    __shared__ __align__(16) float msg[4 * OBS_DEG][ORIG_P];   // 32 rows
    __shared__ __align__(16) float S[4][EMBED];
    __shared__ float apos[4][2];

    if (t < 8) apos[t >> 1][t & 1] = agent_pos[(a0 + (t >> 1)) * 2 + (t & 1)];
    __syncthreads();

    for (int idx = t; idx < 4 * OBS_DEG * ORIG; idx += 128) {
        const int r = idx / ORIG;           // 0..31
        const int k = idx - r * ORIG;
        const int ag = r >> 3;
        const int e  = r & 7;
        const int o = obs_src[(a0 + ag) * OBS_DEG + e];
        float v;
        if (k < IN_DIM) v = obj_x[o * IN_DIM + k];
        else            v = obj_pos[o * POS_DIM + (k - IN_DIM)] - apos[ag][k - IN_DIM];
        msg[r][k] = v;
    }
    __syncthreads();

    ull w1p[9];
#pragma unroll
    for (int q = 0; q < 9; q++)
        w1p[q] = f2pack(W1[(2 * q) * EMBED + t], W1[(2 * q + 1) * EMBED + t]);
    const float b1t = b1[t];

#pragma unroll
    for (int ag = 0; ag < 4; ag++) {
        float acc = 0.f;
#pragma unroll
        for (int e = 0; e < OBS_DEG; e++) {
            const ulonglong2* r = (const ulonglong2*)msg[ag * OBS_DEG + e];
            ulonglong2 q0 = r[0], q1 = r[1], q2 = r[2], q3 = r[3];
            ull q4 = ((const ull*)msg[ag * OBS_DEG + e])[8];
            ull h = 0;
            h = f2fma(q0.x, w1p[0], h); h = f2fma(q0.y, w1p[1], h);
            h = f2fma(q1.x, w1p[2], h); h = f2fma(q1.y, w1p[3], h);
            h = f2fma(q2.x, w1p[4], h); h = f2fma(q2.y, w1p[5], h);
            h = f2fma(q3.x, w1p[6], h); h = f2fma(q3.y, w1p[7], h);
            h = f2fma(q4,   w1p[8], h);
            acc += fmaxf(f2sum(h) + b1t, 0.f);
        }
        S[ag][t] = acc;
    }
    __syncthreads();

    {
        const ulonglong2* WQ = (const ulonglong2*)g_enc_W2Q;
        ull ao[4];
#pragma unroll
        for (int ag = 0; ag < 4; ag++) ao[ag] = 0;
#pragma unroll 4
        for (int kq = 0; kq < 32; kq++) {
            ulonglong2 w = WQ[kq * EMBED + t];
#pragma unroll
            for (int ag = 0; ag < 4; ag++) {
                ulonglong2 z = *(const ulonglong2*)&S[ag][4 * kq];
                ao[ag] = f2fma(z.x, w.x, ao[ag]);
                ao[ag] = f2fma(z.y, w.y, ao[ag]);
            }
        }
        const float b2t = b2[t];
#pragma unroll
        for (int ag = 0; ag < 4; ag++)
            g_enc[(a0 + ag) * EMBED + t] = f2sum(ao[ag]) + b2t;
    }
}

// ---------------------------------------------------------------------------
// K2: per-SOURCE mdec decode, 8 agents per block.
// ---------------------------------------------------------------------------
__global__ __launch_bounds__(128) void mdec_kernel(
    const float* __restrict__ mdec_bs, const float* __restrict__ mdec_bx)
{
    const int j0 = blockIdx.x * 8;
    const int t = threadIdx.x;
    const int lane = t & 31;
    const int wrp  = t >> 5;

    __shared__ __align__(16) float zj[DEG][EMBED];
    __shared__ float psA[32][DEG], psB[32][DEG];
    __shared__ float logitsA[DEG][NLOG], logitsB[DEG][NLOG];

#pragma unroll
    for (int e = 0; e < DEG; e++) zj[e][t] = g_enc[(j0 + e) * EMBED + t];
    __syncthreads();

    {
        const ulonglong2* WQ = (const ulonglong2*)g_mdec_WxQ;
        ull acc0[DEG], acc1[DEG];
#pragma unroll
        for (int e = 0; e < DEG; e++) { acc0[e] = 0; acc1[e] = 0; }
#pragma unroll 2
        for (int kq = 0; kq < 32; kq++) {
            ulonglong2 w0 = WQ[kq * OUTC + t];
            ulonglong2 w1 = WQ[kq * OUTC + t + 128];
#pragma unroll
            for (int e = 0; e < DEG; e++) {
                ulonglong2 z = *(const ulonglong2*)&zj[e][4 * kq];
                acc0[e] = f2fma(z.x, w0.x, acc0[e]);
                acc0[e] = f2fma(z.y, w0.y, acc0[e]);
                acc1[e] = f2fma(z.x, w1.x, acc1[e]);
                acc1[e] = f2fma(z.y, w1.y, acc1[e]);
            }
        }
        const float bx0 = mdec_bx[t];
        const float bx1 = mdec_bx[t + 128];
#pragma unroll
        for (int e = 0; e < DEG; e++) {
            g_elems0[(j0 + e) * OUTC + t]       = f2sum(acc0[e]) + bx0;
            g_elems0[(j0 + e) * OUTC + t + 128] = f2sum(acc1[e]) + bx1;
        }
    }
    {
        const int kq0 = (wrp & 1) ? 16 : 0;
        if (wrp < 2) {
            const int c = 256 + lane;
            const ulonglong2* WQ = (const ulonglong2*)g_mdec_WxQ;
            ull acc[DEG];
#pragma unroll
            for (int e = 0; e < DEG; e++) acc[e] = 0;
#pragma unroll 4
            for (int kq = kq0; kq < kq0 + 16; kq++) {
                ulonglong2 w = WQ[kq * OUTC + c];
#pragma unroll
                for (int e = 0; e < DEG; e++) {
                    ulonglong2 z = *(const ulonglong2*)&zj[e][4 * kq];
                    acc[e] = f2fma(z.x, w.x, acc[e]);
                    acc[e] = f2fma(z.y, w.y, acc[e]);
                }
            }
            if (wrp == 0) {
#pragma unroll
                for (int e = 0; e < DEG; e++) psA[lane][e] = f2sum(acc[e]);
            } else {
#pragma unroll
                for (int e = 0; e < DEG; e++) psB[lane][e] = f2sum(acc[e]);
            }
        } else if (lane < NLOG) {
            const int s = lane;
            const ulonglong2* WsQ = (const ulonglong2*)g_mdec_WsQ;
            ull acc[DEG];
#pragma unroll
            for (int e = 0; e < DEG; e++) acc[e] = 0;
#pragma unroll 4
            for (int kq = kq0; kq < kq0 + 16; kq++) {
                ulonglong2 w = WsQ[kq * NLOG + s];
#pragma unroll
                for (int e = 0; e < DEG; e++) {
                    ulonglong2 z = *(const ulonglong2*)&zj[e][4 * kq];
                    acc[e] = f2fma(z.x, w.x, acc[e]);
                    acc[e] = f2fma(z.y, w.y, acc[e]);
                }
            }
            if (wrp == 2) {
                const float bs = mdec_bs[s];
#pragma unroll
                for (int e = 0; e < DEG; e++) logitsA[e][s] = f2sum(acc[e]) + bs;
            } else {
#pragma unroll
                for (int e = 0; e < DEG; e++) logitsB[e][s] = f2sum(acc[e]);
            }
        }
    }
    __syncthreads();

#pragma unroll
    for (int r = 0; r < 2; r++) {
        const int p = t + r * 128;
        const int cl = p >> 3;
        const int e  = p & 7;
        const int c  = 256 + cl;
        g_elems0[(j0 + e) * OUTC + c] = psA[cl][e] + psB[cl][e] + mdec_bx[c];
    }
    if (t < DEG) {
        float best = logitsA[t][0] + logitsB[t][0]; int bi = 0;
#pragma unroll
        for (int c = 1; c < NLOG; c++) {
            const float v = logitsA[t][c] + logitsB[t][c];
            if (v > best) { best = v; bi = c; }
        }
        g_npred[j0 + t] = bi;
    }
}

// ---------------------------------------------------------------------------
// K3: per-agent gather + dedup + cap + merge-encode -> g_Spre.
// ---------------------------------------------------------------------------
__global__ __launch_bounds__(128) void gather_kernel(
    const float* __restrict__ agent_pos,
    const float* __restrict__ menc_W1, const float* __restrict__ menc_b1,
    const int*   __restrict__ comm_src)
{
    const int i = blockIdx.x;
    const int t = threadIdx.x;
    const int lane = t & 31;
    const int wrp  = t >> 5;

    __shared__ __align__(16) float cand[KTOT][ORIG_P];   // 10 KB
    __shared__ int   npred[DEG];
    __shared__ int   keepf[KTOT];
    __shared__ float cpx[KTOT], cpy[KTOT];
    __shared__ int   cidx[KTOT];
    __shared__ float relx[DEG], rely[DEG];
    __shared__ int   jidx[DEG];
    __shared__ int   kidx[MAX_OBJ];
    __shared__ int   wtot[4], wtot2[4];
    __shared__ int   ncnts;

    if (t < DEG) {
        const int j = comm_src[i * DEG + t];
        jidx[t] = j;
        relx[t] = agent_pos[2 * j    ] - agent_pos[2 * i    ];
        rely[t] = agent_pos[2 * j + 1] - agent_pos[2 * i + 1];
        npred[t] = g_npred[j];
    }
    __syncthreads();

#pragma unroll
    for (int e = 0; e < DEG; e++) {
        const float* src = &g_elems0[jidx[e] * OUTC];
        const float rx = relx[e], ry = rely[e];
        {
            const int c = t, m = c / ORIG, dim = c - m * ORIG;
            float v = src[c];
            if (dim == 16) v += rx;
            if (dim == 17) v += ry;
            cand[e * MAX_OBJ + m][dim] = v;
        }
        {
            const int c = t + 128, m = c / ORIG, dim = c - m * ORIG;
            float v = src[c];
            if (dim == 16) v += rx;
            if (dim == 17) v += ry;
            cand[e * MAX_OBJ + m][dim] = v;
        }
        if (t < 32) {
            const int c = t + 256, m = c / ORIG, dim = c - m * ORIG;
            float v = src[c];
            if (dim == 16) v += rx;
            if (dim == 17) v += ry;
            cand[e * MAX_OBJ + m][dim] = v;
        }
    }
    __syncthreads();

    const int em = t >> 4, mm = t & 15;
    const int v0 = (mm < npred[em]) ? 1 : 0;
    const float x0 = cand[t][16], y0 = cand[t][17];

    unsigned bm = __ballot_sync(0xffffffffu, v0);
    int pre = __popc(bm & ((1u << lane) - 1u));
    if (lane == 31) wtot[wrp] = pre + v0;
    keepf[t] = 0;
    __syncthreads();
    int off = 0;
#pragma unroll
    for (int q = 0; q < 4; q++) if (q < wrp) off += wtot[q];
    const int nv = wtot[0] + wtot[1] + wtot[2] + wtot[3];
    if (v0) { const int p = off + pre; cpx[p] = x0; cpy[p] = y0; cidx[p] = t; }
    __syncthreads();

    if (t < nv) {
        const float xx = cpx[t], yy = cpy[t];
        int dead = 0;
        for (int k = 0; k < t; k++) {
            const float dx = xx - cpx[k];
            const float dy = yy - cpy[k];
            if (sqrtf(fmaf(dx, dx, dy * dy)) < THRES) dead = 1;
        }
        if (!dead) keepf[cidx[t]] = 1;
    }
    __syncthreads();

    const int k2 = keepf[t];
    unsigned bm2 = __ballot_sync(0xffffffffu, k2);
    int pre2 = __popc(bm2 & ((1u << lane) - 1u));
    if (lane == 31) wtot2[wrp] = pre2 + k2;
    __syncthreads();
    int off2 = 0;
#pragma unroll
    for (int q = 0; q < 4; q++) if (q < wrp) off2 += wtot2[q];
    const int tot2 = wtot2[0] + wtot2[1] + wtot2[2] + wtot2[3];
    const int excl = off2 + pre2;
    if (k2 && (excl + 1 <= MAX_OBJ - 1)) kidx[excl] = t;
    if (t == 0) ncnts = (tot2 < MAX_OBJ - 1) ? tot2 : (MAX_OBJ - 1);
    __syncthreads();

    {
        ull w1p[9];
#pragma unroll
        for (int q = 0; q < 9; q++)
            w1p[q] = f2pack(menc_W1[(2 * q) * EMBED + t], menc_W1[(2 * q + 1) * EMBED + t]);
        const float b1t = menc_b1[t];
        const int ncnt = ncnts;
        float acc = 0.f;
        for (int l = 0; l < ncnt; l++) {
            const int li = kidx[l];
            const ulonglong2* r = (const ulonglong2*)cand[li];
            ulonglong2 q0 = r[0], q1 = r[1], q2 = r[2], q3 = r[3];
            ull q4 = ((const ull*)cand[li])[8];
            ull h = 0;
            h = f2fma(q0.x, w1p[0], h); h = f2fma(q0.y, w1p[1], h);
            h = f2fma(q1.x, w1p[2], h); h = f2fma(q1.y, w1p[3], h);
            h = f2fma(q2.x, w1p[4], h); h = f2fma(q2.y, w1p[5], h);
            h = f2fma(q3.x, w1p[6], h); h = f2fma(q3.y, w1p[7], h);
            h = f2fma(q4,   w1p[8], h);
            acc += fmaxf(f2sum(h) + b1t, 0.f);
        }
        g_Spre[i * EMBED + t] = acc;
    }
}

// ---------------------------------------------------------------------------
// K4: 8 agents/block: merged = Spre@menc_W2+b2; n2 = argmax(dec_Ws);
//     out = masked(merged@dec_Wx + bx); batch/mask tails.
// ---------------------------------------------------------------------------
__global__ __launch_bounds__(128) void dec_kernel(
    const float* __restrict__ menc_b2,
    const float* __restrict__ dec_bs, const float* __restrict__ dec_bx,
    float* __restrict__ out, int write_extra)
{
    const int i0 = blockIdx.x * 8;
    const int t = threadIdx.x;
    const int lane = t & 31;
    const int wrp  = t >> 5;

    __shared__ __align__(16) float Sp[DEG][EMBED];
    __shared__ __align__(16) float mg[DEG][EMBED];
    __shared__ float dlog[DEG][NLOG];
    __shared__ int   n2s[DEG];

#pragma unroll
    for (int e = 0; e < DEG; e++) Sp[e][t] = g_Spre[(i0 + e) * EMBED + t];
    __syncthreads();

    // merged: 8 accumulators share each menc_W2 load
    {
        const ulonglong2* WQ = (const ulonglong2*)g_menc_W2Q;
        ull a[DEG];
#pragma unroll
        for (int e = 0; e < DEG; e++) a[e] = 0;
#pragma unroll 2
        for (int kq = 0; kq < 32; kq++) {
            ulonglong2 w = WQ[kq * EMBED + t];
#pragma unroll
            for (int e = 0; e < DEG; e++) {
                ulonglong2 z = *(const ulonglong2*)&Sp[e][4 * kq];
                a[e] = f2fma(z.x, w.x, a[e]);
                a[e] = f2fma(z.y, w.y, a[e]);
            }
        }
        const float b2t = menc_b2[t];
#pragma unroll
        for (int e = 0; e < DEG; e++) mg[e][t] = f2sum(a[e]) + b2t;
    }
    __syncthreads();

    // dec logits: warp w handles agents {2w, 2w+1}, lanes 0..16
    if (lane < NLOG) {
        const ulonglong2* WsQ = (const ulonglong2*)g_dec_WsQ;
        const float bs = dec_bs[lane];
#pragma unroll
        for (int g = 0; g < 2; g++) {
            const int e = wrp * 2 + g;
            ull a = 0;
#pragma unroll 4
            for (int kq = 0; kq < 32; kq++) {
                ulonglong2 w = WsQ[kq * NLOG + lane];
                ulonglong2 z = *(const ulonglong2*)&mg[e][4 * kq];
                a = f2fma(z.x, w.x, a);
                a = f2fma(z.y, w.y, a);
            }
            dlog[e][lane] = f2sum(a) + bs;
        }
    }
    __syncthreads();
    if (t < DEG) {
        float best = dlog[t][0]; int bi = 0;
#pragma unroll
        for (int c = 1; c < NLOG; c++) {
            if (dlog[t][c] > best) { best = dlog[t][c]; bi = c; }
        }
        n2s[t] = bi;
    }
    __syncthreads();

    // dec main: cols {t, t+128} x 8 agents, masked direct writes
    {
        const ulonglong2* WQ = (const ulonglong2*)g_dec_WxQ;
        ull a0[DEG], a1[DEG];
#pragma unroll
        for (int e = 0; e < DEG; e++) { a0[e] = 0; a1[e] = 0; }
#pragma unroll 2
        for (int kq = 0; kq < 32; kq++) {
            ulonglong2 w0 = WQ[kq * OUTC + t];
            ulonglong2 w1 = WQ[kq * OUTC + t + 128];
#pragma unroll
            for (int e = 0; e < DEG; e++) {
                ulonglong2 z = *(const ulonglong2*)&mg[e][4 * kq];
                a0[e] = f2fma(z.x, w0.x, a0[e]);
                a0[e] = f2fma(z.y, w0.y, a0[e]);
                a1[e] = f2fma(z.x, w1.x, a1[e]);
                a1[e] = f2fma(z.y, w1.y, a1[e]);
            }
        }
        const float bx0 = dec_bx[t];
        const float bx1 = dec_bx[t + 128];
        const int m0 = t / ORIG;
        const int m1 = (t + 128) / ORIG;
#pragma unroll
        for (int e = 0; e < DEG; e++) {
            const int n2 = n2s[e];
            out[(size_t)(i0 + e) * OUTC + t]       = (m0 < n2) ? (f2sum(a0[e]) + bx0) : 0.f;
            out[(size_t)(i0 + e) * OUTC + t + 128] = (m1 < n2) ? (f2sum(a1[e]) + bx1) : 0.f;
        }
    }
    // dec tail: warp w does agents {2w, 2w+1}, col 256+lane
    {
        const int c = 256 + lane;
        const int e0 = wrp * 2, e1 = wrp * 2 + 1;
        const ulonglong2* WQ = (const ulonglong2*)g_dec_WxQ;
        ull a0 = 0, a1 = 0;
#pragma unroll 4
        for (int kq = 0; kq < 32; kq++) {
            ulonglong2 w = WQ[kq * OUTC + c];
            ulonglong2 z0 = *(const ulonglong2*)&mg[e0][4 * kq];
            ulonglong2 z1 = *(const ulonglong2*)&mg[e1][4 * kq];
            a0 = f2fma(z0.x, w.x, a0); a0 = f2fma(z0.y, w.y, a0);
            a1 = f2fma(z1.x, w.x, a1); a1 = f2fma(z1.y, w.y, a1);
        }
        const float bx = dec_bx[c];
        const int m = c / ORIG;
        out[(size_t)(i0 + e0) * OUTC + c] = (m < n2s[e0]) ? (f2sum(a0) + bx) : 0.f;
        out[(size_t)(i0 + e1) * OUTC + c] = (m < n2s[e1]) ? (f2sum(a1) + bx) : 0.f;
    }

    // batch + mask tails: 8 agents x 16 = 128 entries
    if (write_extra) {
        const int ag = t >> 4, m = t & 15;
        const size_t batch_off = (size_t)A_N * OUTC;
        const size_t mask_off  = batch_off + (size_t)A_N * MAX_OBJ;
        out[batch_off + (size_t)(i0 + ag) * MAX_OBJ + m] = (float)(i0 + ag);
        out[mask_off  + (size_t)(i0 + ag) * MAX_OBJ + m] = (m < n2s[ag]) ? 1.f : 0.f;
    }
}

extern "C" void kernel_launch(void* const* d_in, const int* in_sizes, int n_in,
                              void* d_out, int out_size) {
    const float* obj_x     = (const float*)d_in[0];
    const float* obj_pos   = (const float*)d_in[1];
    const float* agent_pos = (const float*)d_in[2];
    const float* enc_W1    = (const float*)d_in[3];
    const float* enc_b1    = (const float*)d_in[4];
    const float* enc_W2    = (const float*)d_in[5];
    const float* enc_b2    = (const float*)d_in[6];
    const float* mdec_Ws   = (const float*)d_in[7];
    const float* mdec_bs   = (const float*)d_in[8];
    const float* mdec_Wx   = (const float*)d_in[9];
    const float* mdec_bx   = (const float*)d_in[10];
    const float* menc_W1   = (const float*)d_in[11];
    const float* menc_b1   = (const float*)d_in[12];
    const float* menc_W2   = (const float*)d_in[13];
    const float* menc_b2   = (const float*)d_in[14];
    const float* dec_Ws    = (const float*)d_in[15];
    const float* dec_bs    = (const float*)d_in[16];
    const float* dec_Wx    = (const float*)d_in[17];
    const float* dec_bx    = (const float*)d_in[18];
    const int*   obs_ei    = (const int*)d_in[19];   // row0 = tgt, row1 = src
    const int*   comm_ei   = (const int*)d_in[20];   // row0 = src(j), row1 = tgt(i)

    const int* obs_src  = obs_ei  + A_N * OBS_DEG;   // row 1
    const int* comm_src = comm_ei;                   // row 0

    pre_kernel<<<ENC_BLOCKS + PREP_BLOCKS, 128>>>(obj_x, obj_pos, agent_pos,
                                                  enc_W1, enc_b1, enc_b2, obs_src,
                                                  mdec_Wx, dec_Wx, menc_W2, enc_W2,
                                                  mdec_Ws, dec_Ws);

    mdec_kernel<<<A_N / 8, 128>>>(mdec_bs, mdec_bx);

    gather_kernel<<<A_N, 128>>>(agent_pos, menc_W1, menc_b1, comm_src);

    const int full = A_N * OUTC + 2 * A_N * MAX_OBJ;   // decoded + batch + mask
    const int write_extra = (out_size >= full) ? 1 : 0;

    dec_kernel<<<A_N / 8, 128>>>(menc_b2, dec_bs, dec_bx,
                                 (float*)d_out, write_extra);
}